// round 12
// baseline (speedup 1.0000x reference)
#include <cuda_runtime.h>
#include <cuda_bf16.h>
#include <mma.h>
#include <math.h>
#include <stdint.h>

using namespace nvcuda;

// Problem constants
#define B_ 2
#define L_ 2048
#define D_ 1024
#define F_ 4096
#define H_ 16
#define HD_ 64
#define M_ (B_ * L_)
#define LN_EPS 1e-6f

// ---------------------------------------------------------------------------
// Scratch (static device globals; no allocation anywhere)
// ---------------------------------------------------------------------------
__device__ __nv_bfloat16 g_h_hi[M_ * D_];
__device__ __nv_bfloat16 g_h_lo[M_ * D_];
__device__ __nv_bfloat16 g_qkv_hi[M_ * 3 * D_];
__device__ __nv_bfloat16 g_qkv_lo[M_ * 3 * D_];
__device__ __nv_bfloat16 g_at_hi[M_ * D_];
__device__ __nv_bfloat16 g_at_lo[M_ * D_];
__device__ float         g_x1[M_ * D_];
__device__ __nv_bfloat16 g_mid_hi[M_ * F_];
__device__ __nv_bfloat16 g_mid_lo[M_ * F_];
// weights transposed to [N][K], split hi/lo
__device__ __nv_bfloat16 g_wqkv_hi[3 * D_ * D_];
__device__ __nv_bfloat16 g_wqkv_lo[3 * D_ * D_];
__device__ __nv_bfloat16 g_wpr_hi[D_ * D_];
__device__ __nv_bfloat16 g_wpr_lo[D_ * D_];
__device__ __nv_bfloat16 g_wm1_hi[F_ * D_];
__device__ __nv_bfloat16 g_wm1_lo[F_ * D_];
__device__ __nv_bfloat16 g_wm2_hi[D_ * F_];
__device__ __nv_bfloat16 g_wm2_lo[D_ * F_];

// ---------------------------------------------------------------------------
// helpers
// ---------------------------------------------------------------------------
__device__ __forceinline__ uint32_t smem_to_u32(const void* p) {
    uint32_t a;
    asm("{ .reg .u64 t; cvta.to.shared.u64 t, %1; cvt.u32.u64 %0, t; }"
        : "=r"(a) : "l"(p));
    return a;
}

__device__ __forceinline__ void cp16(uint32_t daddr, const void* g) {
    asm volatile("cp.async.cg.shared.global [%0], [%1], 16;"
                 :: "r"(daddr), "l"(g));
}
#define CP_COMMIT() asm volatile("cp.async.commit_group;" ::: "memory")
template <int N>
__device__ __forceinline__ void cp_wait_group() {
    asm volatile("cp.async.wait_group %0;" :: "n"(N) : "memory");
}

__device__ __forceinline__ uint32_t bf2u(__nv_bfloat16 a, __nv_bfloat16 b) {
    return (uint32_t)__bfloat16_as_ushort(a) |
           ((uint32_t)__bfloat16_as_ushort(b) << 16);
}

__device__ __forceinline__ void split_store4(
    __nv_bfloat16* __restrict__ hi, __nv_bfloat16* __restrict__ lo,
    size_t off, float a, float b, float c, float d)
{
    __nv_bfloat16 h0 = __float2bfloat16(a), h1 = __float2bfloat16(b);
    __nv_bfloat16 h2 = __float2bfloat16(c), h3 = __float2bfloat16(d);
    __nv_bfloat16 l0 = __float2bfloat16(a - __bfloat162float(h0));
    __nv_bfloat16 l1 = __float2bfloat16(b - __bfloat162float(h1));
    __nv_bfloat16 l2 = __float2bfloat16(c - __bfloat162float(h2));
    __nv_bfloat16 l3 = __float2bfloat16(d - __bfloat162float(h3));
    *(uint2*)(hi + off) = make_uint2(bf2u(h0, h1), bf2u(h2, h3));
    *(uint2*)(lo + off) = make_uint2(bf2u(l0, l1), bf2u(l2, l3));
}

__device__ __forceinline__ float gelu_tanh(float v) {
    const float c = 0.7978845608028654f;
    float u = c * (v + 0.044715f * v * v * v);
    return 0.5f * v * (1.0f + tanhf(u));
}

// ---------------------------------------------------------------------------
// Weight transpose + split: W[K][N] -> hi/lo[N][K] bf16
// ---------------------------------------------------------------------------
__global__ __launch_bounds__(256) void wsplit_t(
    const float* __restrict__ W, __nv_bfloat16* __restrict__ hi,
    __nv_bfloat16* __restrict__ lo, int K, int N)
{
    __shared__ float t[32][33];
    const int n0 = blockIdx.x * 32, k0 = blockIdx.y * 32;
    const int tx = threadIdx.x, ty = threadIdx.y;
    #pragma unroll
    for (int i = ty; i < 32; i += 8)
        t[i][tx] = W[(size_t)(k0 + i) * N + n0 + tx];
    __syncthreads();
    #pragma unroll
    for (int i = ty; i < 32; i += 8) {
        const float v = t[tx][i];
        const __nv_bfloat16 h = __float2bfloat16(v);
        const __nv_bfloat16 l = __float2bfloat16(v - __bfloat162float(h));
        const size_t o = (size_t)(n0 + i) * K + k0 + tx;
        hi[o] = h; lo[o] = l;
    }
}

// ---------------------------------------------------------------------------
// LayerNorm -> bf16 hi/lo
// ---------------------------------------------------------------------------
__global__ __launch_bounds__(256) void layernorm_k(
    const float* __restrict__ x, const float* __restrict__ gamma,
    const float* __restrict__ beta,
    __nv_bfloat16* __restrict__ ohi, __nv_bfloat16* __restrict__ olo)
{
    const int row = blockIdx.x;
    const int t = threadIdx.x;
    const float4 v = *(const float4*)(x + (size_t)row * D_ + t * 4);

    float s = v.x + v.y + v.z + v.w;
    float q = v.x * v.x + v.y * v.y + v.z * v.z + v.w * v.w;
    #pragma unroll
    for (int off = 16; off > 0; off >>= 1) {
        s += __shfl_down_sync(0xffffffffu, s, off);
        q += __shfl_down_sync(0xffffffffu, q, off);
    }
    __shared__ float ss[8], qq[8];
    const int wid = t >> 5, lane = t & 31;
    if (lane == 0) { ss[wid] = s; qq[wid] = q; }
    __syncthreads();
    if (t == 0) {
        float S = 0.f, Q = 0.f;
        #pragma unroll
        for (int i = 0; i < 8; i++) { S += ss[i]; Q += qq[i]; }
        ss[0] = S; qq[0] = Q;
    }
    __syncthreads();
    const float mu = ss[0] * (1.0f / D_);
    const float var = qq[0] * (1.0f / D_) - mu * mu;
    const float rstd = rsqrtf(var + LN_EPS);

    const float4 g4 = *(const float4*)(gamma + t * 4);
    const float4 b4 = *(const float4*)(beta + t * 4);
    const float ox = (v.x - mu) * rstd * g4.x + b4.x;
    const float oy = (v.y - mu) * rstd * g4.y + b4.y;
    const float oz = (v.z - mu) * rstd * g4.z + b4.z;
    const float ow = (v.w - mu) * rstd * g4.w + b4.w;
    split_store4(ohi, olo, (size_t)row * D_ + t * 4, ox, oy, oz, ow);
}

// ---------------------------------------------------------------------------
// WMMA GEMM (unchanged from R10): bf16x3, 128x256 tile, 3-stage cp.async.
// EPI: 0 = fp32 out, 1 = +bias +residual -> fp32,
//      2 = +bias +gelu -> bf16 hi/lo, 3 = split -> bf16 hi/lo (no bias)
// ---------------------------------------------------------------------------
#define BM 128
#define BN 256
#define BK 32
#define NSTAGE 3
#define LDS_ 40
#define A_EL (128 * LDS_)
#define B_EL (256 * LDS_)
#define STAGE_EL (2 * A_EL + 2 * B_EL)
#define EPI_LD 260
#define GEMM_SMEM (NSTAGE * STAGE_EL * 2)

template <int EPI>
__global__ __launch_bounds__(256, 1) void wm_gemm(
    const __nv_bfloat16* __restrict__ Ahi, const __nv_bfloat16* __restrict__ Alo,
    const __nv_bfloat16* __restrict__ Bhi, const __nv_bfloat16* __restrict__ Blo,
    const float* __restrict__ bias, const float* __restrict__ res,
    float* __restrict__ C, __nv_bfloat16* __restrict__ Chi,
    __nv_bfloat16* __restrict__ Clo, int M, int N, int K)
{
    extern __shared__ char smem[];
    __nv_bfloat16* sb = (__nv_bfloat16*)smem;
    const uint32_t sbase = smem_to_u32(smem);
    const int tid = threadIdx.x;
    const int w = tid >> 5;
    const int wm = w >> 2;
    const int wn = w & 3;
    const int mBase = blockIdx.y * BM;
    const int nBase = blockIdx.x * BN;

    const __nv_bfloat16* gsrc[4] = {
        Ahi + (size_t)mBase * K,
        Alo + (size_t)mBase * K,
        Bhi + (size_t)nBase * K,
        Blo + (size_t)nBase * K };
    const int unit_of_it[12]  = {0,0, 1,1, 2,2,2,2, 3,3,3,3};
    const int rbase_of_it[12] = {0,0, 128,128, 256,256,256,256, 512,512,512,512};
    const int soff_of_unit[4] = {0, A_EL, 2 * A_EL, 2 * A_EL + B_EL};

    wmma::fragment<wmma::accumulator, 16, 16, 16, float> acc[4][4];
    #pragma unroll
    for (int i = 0; i < 4; i++)
        #pragma unroll
        for (int j = 0; j < 4; j++)
            wmma::fill_fragment(acc[i][j], 0.0f);

    const int nchunks = K / BK;

    auto load_stage = [&](int stg, int k0) {
        const uint32_t so = sbase + (uint32_t)stg * STAGE_EL * 2;
        #pragma unroll
        for (int it = 0; it < 12; it++) {
            const int idx = it * 256 + tid;
            const int r = idx >> 2;
            const int seg = idx & 3;
            const int u = unit_of_it[it];
            const int lr = r - rbase_of_it[it];
            cp16(so + (uint32_t)(soff_of_unit[u] + lr * LDS_ + seg * 8) * 2,
                 gsrc[u] + (size_t)lr * K + k0 + seg * 8);
        }
    };

    load_stage(0, 0);
    CP_COMMIT();
    load_stage(1, BK);
    CP_COMMIT();

    int s = 0, sl = 2;
    for (int c = 0; c < nchunks; c++) {
        cp_wait_group<1>();
        __syncthreads();
        if (c + 2 < nchunks) {
            load_stage(sl, (c + 2) * BK);
            CP_COMMIT();
        }
        const __nv_bfloat16* st = sb + s * STAGE_EL;
        const __nv_bfloat16* sAh = st;
        const __nv_bfloat16* sAl = st + A_EL;
        const __nv_bfloat16* sBh = st + 2 * A_EL;
        const __nv_bfloat16* sBl = st + 2 * A_EL + B_EL;

        #pragma unroll
        for (int kk = 0; kk < BK; kk += 16) {
            wmma::fragment<wmma::matrix_b, 16, 16, 16, __nv_bfloat16,
                           wmma::col_major> bh[4], bl[4];
            #pragma unroll
            for (int j = 0; j < 4; j++) {
                wmma::load_matrix_sync(bh[j],
                    sBh + (wn * 64 + j * 16) * LDS_ + kk, LDS_);
                wmma::load_matrix_sync(bl[j],
                    sBl + (wn * 64 + j * 16) * LDS_ + kk, LDS_);
            }
            #pragma unroll
            for (int i = 0; i < 4; i++) {
                wmma::fragment<wmma::matrix_a, 16, 16, 16, __nv_bfloat16,
                               wmma::row_major> ah, al;
                wmma::load_matrix_sync(ah,
                    sAh + (wm * 64 + i * 16) * LDS_ + kk, LDS_);
                wmma::load_matrix_sync(al,
                    sAl + (wm * 64 + i * 16) * LDS_ + kk, LDS_);
                #pragma unroll
                for (int j = 0; j < 4; j++) {
                    wmma::mma_sync(acc[i][j], ah, bh[j], acc[i][j]);
                    wmma::mma_sync(acc[i][j], ah, bl[j], acc[i][j]);
                    wmma::mma_sync(acc[i][j], al, bh[j], acc[i][j]);
                }
            }
        }
        s = (s == NSTAGE - 1) ? 0 : s + 1;
        sl = (sl == NSTAGE - 1) ? 0 : sl + 1;
    }

    __syncthreads();
    float* sf = (float*)smem;
    #pragma unroll
    for (int i = 0; i < 4; i++)
        #pragma unroll
        for (int j = 0; j < 4; j++)
            wmma::store_matrix_sync(
                sf + (wm * 64 + i * 16) * EPI_LD + wn * 64 + j * 16,
                acc[i][j], EPI_LD, wmma::mem_row_major);
    __syncthreads();

    #pragma unroll 4
    for (int it = 0; it < 32; it++) {
        const int idx = tid + it * 256;
        const int rr = idx >> 6;
        const int c4 = (idx & 63) * 4;
        float4 v = *(const float4*)&sf[rr * EPI_LD + c4];
        const int m = mBase + rr;
        const int n = nBase + c4;
        if (EPI == 1 || EPI == 2) {
            const float4 bi = *(const float4*)(bias + n);
            v.x += bi.x; v.y += bi.y; v.z += bi.z; v.w += bi.w;
        }
        if (EPI == 2) {
            v.x = gelu_tanh(v.x); v.y = gelu_tanh(v.y);
            v.z = gelu_tanh(v.z); v.w = gelu_tanh(v.w);
            split_store4(Chi, Clo, (size_t)m * N + n, v.x, v.y, v.z, v.w);
        } else if (EPI == 3) {
            split_store4(Chi, Clo, (size_t)m * N + n, v.x, v.y, v.z, v.w);
        } else {
            if (EPI == 1) {
                const float4 rv = *(const float4*)(res + (size_t)m * N + n);
                v.x += rv.x; v.y += rv.y; v.z += rv.z; v.w += rv.w;
            }
            *(float4*)(C + (size_t)m * N + n) = v;
        }
    }
}

// ---------------------------------------------------------------------------
// WMMA flash attention v2: Q block 64, KV block 128, 256 threads (8 warps).
// S phase: 2x4 warp grid of 32x32 over S[64][128].
// PV phase: 4x2 warp grid of 16x32 over O[64][64].
// Next KV chunk prefetched (single-buffered) right after the PV barrier.
// ---------------------------------------------------------------------------
#define FQ_LD 72                         // bf16 ld (144B rows)
#define PLD   136                        // P bf16 ld (272B rows)
#define SLD   132                        // S fp32 ld (528B rows)
#define OLD   68                         // O fp32 ld (272B rows)
#define OFF_QH 0
#define OFF_QL 9216
#define OFF_KH 18432
#define OFF_KL 36864
#define OFF_VH 55296
#define OFF_VL 73728
#define OFF_PH 92160
#define OFF_PL 109568
#define OFF_S  126976
#define OFF_O  160768
#define OFF_M  178176
#define OFF_L  178432
#define OFF_C  178688
#define FAW_SMEM 178944

__global__ __launch_bounds__(256) void flash_attn_w(
    const __nv_bfloat16* __restrict__ qkvh,
    const __nv_bfloat16* __restrict__ qkvl,
    __nv_bfloat16* __restrict__ ohi, __nv_bfloat16* __restrict__ olo)
{
    extern __shared__ char sm8[];
    __nv_bfloat16* sQh = (__nv_bfloat16*)(sm8 + OFF_QH);
    __nv_bfloat16* sQl = (__nv_bfloat16*)(sm8 + OFF_QL);
    __nv_bfloat16* sKh = (__nv_bfloat16*)(sm8 + OFF_KH);
    __nv_bfloat16* sKl = (__nv_bfloat16*)(sm8 + OFF_KL);
    __nv_bfloat16* sVh = (__nv_bfloat16*)(sm8 + OFF_VH);
    __nv_bfloat16* sVl = (__nv_bfloat16*)(sm8 + OFF_VL);
    __nv_bfloat16* sPh = (__nv_bfloat16*)(sm8 + OFF_PH);
    __nv_bfloat16* sPl = (__nv_bfloat16*)(sm8 + OFF_PL);
    float* sS    = (float*)(sm8 + OFF_S);
    float* sO    = (float*)(sm8 + OFF_O);
    float* mrun  = (float*)(sm8 + OFF_M);
    float* lrun  = (float*)(sm8 + OFF_L);
    float* corrA = (float*)(sm8 + OFF_C);

    const int b = blockIdx.z, h = blockIdx.y;
    const int qb = blockIdx.x * 64;
    const int tid = threadIdx.x;
    const int w = tid >> 5;
    const uint32_t sbase = smem_to_u32(sm8);

    // S-phase warp grid (2 x 4 of 32x32); PV-phase warp grid (4 x 2 of 16x32)
    const int wmS = w >> 2, wnS = w & 3;
    const int wmO = w >> 1, wnO = w & 1;
    // softmax / O-update mapping: 4 threads per row
    const int r = tid >> 2;
    const int q = tid & 3;

    // async-load Q hi/lo (64 x 64 bf16 each): 512 cp16 per tensor
    {
        const size_t qoff = (size_t)(b * L_ + qb) * (3 * D_) + h * HD_;
        #pragma unroll
        for (int it = 0; it < 2; it++) {
            const int i = it * 256 + tid;          // 0..511
            const int rr = i >> 3, seg = i & 7;
            const uint32_t so = (uint32_t)(rr * FQ_LD + seg * 8) * 2;
            const size_t g = qoff + (size_t)rr * (3 * D_) + seg * 8;
            cp16(sbase + OFF_QH + so, qkvh + g);
            cp16(sbase + OFF_QL + so, qkvl + g);
        }
        CP_COMMIT();
    }
    // zero O, init stats
    for (int i = tid; i < 64 * OLD; i += 256) sO[i] = 0.0f;
    if (tid < 64) { mrun[tid] = -INFINITY; lrun[tid] = 0.0f; }

    // KV loader: 4 tensors x 128 rows x 8 segs = 4096 cp16 -> 16 per thread
    auto load_kv = [&](int kb) {
        const size_t koff = (size_t)(b * L_ + kb) * (3 * D_) + D_ + h * HD_;
        #pragma unroll
        for (int it = 0; it < 16; it++) {
            const int i = it * 256 + tid;          // 0..4095
            const int u = i >> 10;                 // 0..3
            const int rr = (i >> 3) & 127;
            const int seg = i & 7;
            const uint32_t so = (uint32_t)(rr * FQ_LD + seg * 8) * 2;
            const size_t g = koff + (size_t)rr * (3 * D_) + seg * 8
                             + ((u >= 2) ? D_ : 0);
            const uint32_t doff = (u == 0) ? OFF_KH : (u == 1) ? OFF_KL
                                : (u == 2) ? OFF_VH : OFF_VL;
            cp16(sbase + doff + so, ((u & 1) ? qkvl : qkvh) + g);
        }
        CP_COMMIT();
    };

    load_kv(0);
    cp_wait_group<0>();
    __syncthreads();

    for (int it16 = 0; it16 < L_ / 128; it16++) {
        // ---- S = Q K^T (bf16x3): warp tile 32x32, S[64][128] ----
        {
            wmma::fragment<wmma::accumulator, 16, 16, 16, float> sa[2][2];
            #pragma unroll
            for (int i = 0; i < 2; i++)
                #pragma unroll
                for (int j = 0; j < 2; j++) wmma::fill_fragment(sa[i][j], 0.0f);
            #pragma unroll
            for (int d = 0; d < HD_; d += 16) {
                wmma::fragment<wmma::matrix_b, 16, 16, 16, __nv_bfloat16,
                               wmma::col_major> bh[2], bl[2];
                #pragma unroll
                for (int j = 0; j < 2; j++) {
                    wmma::load_matrix_sync(bh[j],
                        sKh + (wnS * 32 + j * 16) * FQ_LD + d, FQ_LD);
                    wmma::load_matrix_sync(bl[j],
                        sKl + (wnS * 32 + j * 16) * FQ_LD + d, FQ_LD);
                }
                #pragma unroll
                for (int i = 0; i < 2; i++) {
                    wmma::fragment<wmma::matrix_a, 16, 16, 16, __nv_bfloat16,
                                   wmma::row_major> ah, al;
                    wmma::load_matrix_sync(ah,
                        sQh + (wmS * 32 + i * 16) * FQ_LD + d, FQ_LD);
                    wmma::load_matrix_sync(al,
                        sQl + (wmS * 32 + i * 16) * FQ_LD + d, FQ_LD);
                    #pragma unroll
                    for (int j = 0; j < 2; j++) {
                        wmma::mma_sync(sa[i][j], ah, bh[j], sa[i][j]);
                        wmma::mma_sync(sa[i][j], ah, bl[j], sa[i][j]);
                        wmma::mma_sync(sa[i][j], al, bh[j], sa[i][j]);
                    }
                }
            }
            #pragma unroll
            for (int i = 0; i < 2; i++)
                #pragma unroll
                for (int j = 0; j < 2; j++)
                    wmma::store_matrix_sync(
                        sS + (wmS * 32 + i * 16) * SLD + wnS * 32 + j * 16,
                        sa[i][j], SLD, wmma::mem_row_major);
        }
        __syncthreads();

        // ---- online softmax (4 threads/row, 32 cols each) ----
        {
            float sv[32];
            float tmax = -INFINITY;
            #pragma unroll
            for (int g = 0; g < 8; g++) {
                const float4 f = *(const float4*)&sS[r * SLD + q * 32 + g * 4];
                sv[g * 4 + 0] = f.x * 0.125f; sv[g * 4 + 1] = f.y * 0.125f;
                sv[g * 4 + 2] = f.z * 0.125f; sv[g * 4 + 3] = f.w * 0.125f;
                tmax = fmaxf(tmax, fmaxf(fmaxf(sv[g*4], sv[g*4+1]),
                                         fmaxf(sv[g*4+2], sv[g*4+3])));
            }
            tmax = fmaxf(tmax, __shfl_xor_sync(0xffffffffu, tmax, 1));
            tmax = fmaxf(tmax, __shfl_xor_sync(0xffffffffu, tmax, 2));
            const float mold = mrun[r];
            const float mnew = fmaxf(mold, tmax);
            const float corr = __expf(mold - mnew);
            float rsum = 0.f;
            #pragma unroll
            for (int g = 0; g < 8; g++) {
                const float p0 = __expf(sv[g*4+0] - mnew);
                const float p1 = __expf(sv[g*4+1] - mnew);
                const float p2 = __expf(sv[g*4+2] - mnew);
                const float p3 = __expf(sv[g*4+3] - mnew);
                rsum += (p0 + p1) + (p2 + p3);
                split_store4(sPh, sPl, (size_t)r * PLD + q * 32 + g * 4,
                             p0, p1, p2, p3);
            }
            rsum += __shfl_xor_sync(0xffffffffu, rsum, 1);
            rsum += __shfl_xor_sync(0xffffffffu, rsum, 2);
            if (q == 0) {
                lrun[r] = lrun[r] * corr + rsum;
                mrun[r] = mnew;
                corrA[r] = corr;
            }
        }
        __syncthreads();

        // ---- Od = P V (bf16x3): warp tile 16x32 over O[64][64] ----
        {
            wmma::fragment<wmma::accumulator, 16, 16, 16, float> oa[2];
            #pragma unroll
            for (int j = 0; j < 2; j++) wmma::fill_fragment(oa[j], 0.0f);
            #pragma unroll
            for (int kk = 0; kk < 128; kk += 16) {
                wmma::fragment<wmma::matrix_b, 16, 16, 16, __nv_bfloat16,
                               wmma::row_major> bh[2], bl[2];
                #pragma unroll
                for (int j = 0; j < 2; j++) {
                    wmma::load_matrix_sync(bh[j],
                        sVh + kk * FQ_LD + wnO * 32 + j * 16, FQ_LD);
                    wmma::load_matrix_sync(bl[j],
                        sVl + kk * FQ_LD + wnO * 32 + j * 16, FQ_LD);
                }
                wmma::fragment<wmma::matrix_a, 16, 16, 16, __nv_bfloat16,
                               wmma::row_major> ah, al;
                wmma::load_matrix_sync(ah, sPh + (wmO * 16) * PLD + kk, PLD);
                wmma::load_matrix_sync(al, sPl + (wmO * 16) * PLD + kk, PLD);
                #pragma unroll
                for (int j = 0; j < 2; j++) {
                    wmma::mma_sync(oa[j], ah, bh[j], oa[j]);
                    wmma::mma_sync(oa[j], ah, bl[j], oa[j]);
                    wmma::mma_sync(oa[j], al, bh[j], oa[j]);
                }
            }
            #pragma unroll
            for (int j = 0; j < 2; j++)
                wmma::store_matrix_sync(
                    sS + (wmO * 16) * SLD + wnO * 32 + j * 16,
                    oa[j], SLD, wmma::mem_row_major);
        }
        __syncthreads();

        // prefetch next KV (K/V buffers are dead now), overlap with O-update
        if (it16 + 1 < L_ / 128) load_kv((it16 + 1) * 128);

        // ---- O = O * corr + Od (16 cols per thread) ----
        {
            const float corr = corrA[r];
            #pragma unroll
            for (int g = 0; g < 4; g++) {
                const int os = r * SLD + q * 16 + g * 4;
                const int oo = r * OLD + q * 16 + g * 4;
                float4 ov = *(const float4*)&sO[oo];
                const float4 dv = *(const float4*)&sS[os];
                ov.x = ov.x * corr + dv.x; ov.y = ov.y * corr + dv.y;
                ov.z = ov.z * corr + dv.z; ov.w = ov.w * corr + dv.w;
                *(float4*)&sO[oo] = ov;
            }
        }
        cp_wait_group<0>();
        __syncthreads();
    }

    // normalize + split-store (16 cols per thread)
    {
        const float inv = 1.0f / lrun[r];
        #pragma unroll
        for (int g = 0; g < 4; g++) {
            const float4 ov = *(const float4*)&sO[r * OLD + q * 16 + g * 4];
            split_store4(ohi, olo,
                (size_t)(b * L_ + qb + r) * D_ + h * HD_ + q * 16 + g * 4,
                ov.x * inv, ov.y * inv, ov.z * inv, ov.w * inv);
        }
    }
}

// ---------------------------------------------------------------------------
// Launch
// ---------------------------------------------------------------------------
extern "C" void kernel_launch(void* const* d_in, const int* in_sizes, int n_in,
                              void* d_out, int out_size)
{
    const float* x      = (const float*)d_in[0];
    const float* ln1_s  = (const float*)d_in[1];
    const float* ln1_b  = (const float*)d_in[2];
    const float* w_qkv  = (const float*)d_in[3];
    const float* w_proj = (const float*)d_in[4];
    const float* b_proj = (const float*)d_in[5];
    const float* ln2_s  = (const float*)d_in[6];
    const float* ln2_b  = (const float*)d_in[7];
    const float* w_mlp1 = (const float*)d_in[8];
    const float* b_mlp1 = (const float*)d_in[9];
    const float* w_mlp2 = (const float*)d_in[10];
    const float* b_mlp2 = (const float*)d_in[11];
    float* out = (float*)d_out;

    __nv_bfloat16 *hhi, *hlo, *qkvh, *qkvl, *athi, *atlo, *midhi, *midlo;
    __nv_bfloat16 *wqh, *wql, *wph, *wpl, *w1h, *w1l, *w2h, *w2l;
    float *x1;
    cudaGetSymbolAddress((void**)&hhi, g_h_hi);
    cudaGetSymbolAddress((void**)&hlo, g_h_lo);
    cudaGetSymbolAddress((void**)&qkvh, g_qkv_hi);
    cudaGetSymbolAddress((void**)&qkvl, g_qkv_lo);
    cudaGetSymbolAddress((void**)&athi, g_at_hi);
    cudaGetSymbolAddress((void**)&atlo, g_at_lo);
    cudaGetSymbolAddress((void**)&x1, g_x1);
    cudaGetSymbolAddress((void**)&midhi, g_mid_hi);
    cudaGetSymbolAddress((void**)&midlo, g_mid_lo);
    cudaGetSymbolAddress((void**)&wqh, g_wqkv_hi);
    cudaGetSymbolAddress((void**)&wql, g_wqkv_lo);
    cudaGetSymbolAddress((void**)&wph, g_wpr_hi);
    cudaGetSymbolAddress((void**)&wpl, g_wpr_lo);
    cudaGetSymbolAddress((void**)&w1h, g_wm1_hi);
    cudaGetSymbolAddress((void**)&w1l, g_wm1_lo);
    cudaGetSymbolAddress((void**)&w2h, g_wm2_hi);
    cudaGetSymbolAddress((void**)&w2l, g_wm2_lo);

    static bool attr_set = false;
    if (!attr_set) {
        cudaFuncSetAttribute(flash_attn_w,
            cudaFuncAttributeMaxDynamicSharedMemorySize, FAW_SMEM);
        cudaFuncSetAttribute(wm_gemm<1>,
            cudaFuncAttributeMaxDynamicSharedMemorySize, GEMM_SMEM);
        cudaFuncSetAttribute(wm_gemm<2>,
            cudaFuncAttributeMaxDynamicSharedMemorySize, GEMM_SMEM);
        cudaFuncSetAttribute(wm_gemm<3>,
            cudaFuncAttributeMaxDynamicSharedMemorySize, GEMM_SMEM);
        attr_set = true;
    }

    const dim3 tb(32, 8);
    wsplit_t<<<dim3(3 * D_ / 32, D_ / 32), tb>>>(w_qkv, wqh, wql, D_, 3 * D_);
    wsplit_t<<<dim3(D_ / 32, D_ / 32), tb>>>(w_proj, wph, wpl, D_, D_);
    wsplit_t<<<dim3(F_ / 32, D_ / 32), tb>>>(w_mlp1, w1h, w1l, D_, F_);
    wsplit_t<<<dim3(D_ / 32, F_ / 32), tb>>>(w_mlp2, w2h, w2l, F_, D_);

    // 1) pre-norm 1 -> bf16 hi/lo
    layernorm_k<<<M_, 256>>>(x, ln1_s, ln1_b, hhi, hlo);
    // 2) qkv projection -> bf16 hi/lo directly
    wm_gemm<3><<<dim3(3 * D_ / BN, M_ / BM), 256, GEMM_SMEM>>>(
        hhi, hlo, wqh, wql, nullptr, nullptr, nullptr, qkvh, qkvl,
        M_, 3 * D_, D_);
    // 3) attention (wmma bf16x3, KV=128) -> bf16 hi/lo
    flash_attn_w<<<dim3(L_ / 64, H_, B_), 256, FAW_SMEM>>>(
        qkvh, qkvl, athi, atlo);
    // 4) out proj + bias + residual -> fp32 x1
    wm_gemm<1><<<dim3(D_ / BN, M_ / BM), 256, GEMM_SMEM>>>(
        athi, atlo, wph, wpl, b_proj, x, x1, nullptr, nullptr,
        M_, D_, D_);
    // 5) pre-norm 2 -> bf16 hi/lo
    layernorm_k<<<M_, 256>>>(x1, ln2_s, ln2_b, hhi, hlo);
    // 6) MLP up + bias + gelu -> bf16 hi/lo
    wm_gemm<2><<<dim3(F_ / BN, M_ / BM), 256, GEMM_SMEM>>>(
        hhi, hlo, w1h, w1l, b_mlp1, nullptr, nullptr, midhi, midlo,
        M_, F_, D_);
    // 7) MLP down + bias + residual -> final out
    wm_gemm<1><<<dim3(D_ / BN, M_ / BM), 256, GEMM_SMEM>>>(
        midhi, midlo, w2h, w2l, b_mlp2, x1, out, nullptr, nullptr,
        M_, D_, F_);
}

// round 13
// speedup vs baseline: 1.0623x; 1.0623x over previous
#include <cuda_runtime.h>
#include <cuda_bf16.h>
#include <mma.h>
#include <math.h>
#include <stdint.h>

using namespace nvcuda;

// Problem constants
#define B_ 2
#define L_ 2048
#define D_ 1024
#define F_ 4096
#define H_ 16
#define HD_ 64
#define M_ (B_ * L_)
#define LN_EPS 1e-6f

// ---------------------------------------------------------------------------
// Scratch (static device globals; no allocation anywhere)
// ---------------------------------------------------------------------------
__device__ __nv_bfloat16 g_h_hi[M_ * D_];
__device__ __nv_bfloat16 g_h_lo[M_ * D_];
__device__ __nv_bfloat16 g_qkv_hi[M_ * 3 * D_];
__device__ __nv_bfloat16 g_qkv_lo[M_ * 3 * D_];
__device__ __nv_bfloat16 g_at_hi[M_ * D_];
__device__ __nv_bfloat16 g_at_lo[M_ * D_];
__device__ float         g_x1[M_ * D_];
__device__ __nv_bfloat16 g_mid_hi[M_ * F_];
__device__ __nv_bfloat16 g_mid_lo[M_ * F_];
// weights transposed to [N][K], split hi/lo
__device__ __nv_bfloat16 g_wqkv_hi[3 * D_ * D_];
__device__ __nv_bfloat16 g_wqkv_lo[3 * D_ * D_];
__device__ __nv_bfloat16 g_wpr_hi[D_ * D_];
__device__ __nv_bfloat16 g_wpr_lo[D_ * D_];
__device__ __nv_bfloat16 g_wm1_hi[F_ * D_];
__device__ __nv_bfloat16 g_wm1_lo[F_ * D_];
__device__ __nv_bfloat16 g_wm2_hi[D_ * F_];
__device__ __nv_bfloat16 g_wm2_lo[D_ * F_];

// ---------------------------------------------------------------------------
// helpers
// ---------------------------------------------------------------------------
__device__ __forceinline__ uint32_t smem_to_u32(const void* p) {
    uint32_t a;
    asm("{ .reg .u64 t; cvta.to.shared.u64 t, %1; cvt.u32.u64 %0, t; }"
        : "=r"(a) : "l"(p));
    return a;
}

__device__ __forceinline__ void cp16(uint32_t daddr, const void* g) {
    asm volatile("cp.async.cg.shared.global [%0], [%1], 16;"
                 :: "r"(daddr), "l"(g));
}
#define CP_COMMIT() asm volatile("cp.async.commit_group;" ::: "memory")
template <int N>
__device__ __forceinline__ void cp_wait_group() {
    asm volatile("cp.async.wait_group %0;" :: "n"(N) : "memory");
}

__device__ __forceinline__ uint32_t bf2u(__nv_bfloat16 a, __nv_bfloat16 b) {
    return (uint32_t)__bfloat16_as_ushort(a) |
           ((uint32_t)__bfloat16_as_ushort(b) << 16);
}

__device__ __forceinline__ void split_store4(
    __nv_bfloat16* __restrict__ hi, __nv_bfloat16* __restrict__ lo,
    size_t off, float a, float b, float c, float d)
{
    __nv_bfloat16 h0 = __float2bfloat16(a), h1 = __float2bfloat16(b);
    __nv_bfloat16 h2 = __float2bfloat16(c), h3 = __float2bfloat16(d);
    __nv_bfloat16 l0 = __float2bfloat16(a - __bfloat162float(h0));
    __nv_bfloat16 l1 = __float2bfloat16(b - __bfloat162float(h1));
    __nv_bfloat16 l2 = __float2bfloat16(c - __bfloat162float(h2));
    __nv_bfloat16 l3 = __float2bfloat16(d - __bfloat162float(h3));
    *(uint2*)(hi + off) = make_uint2(bf2u(h0, h1), bf2u(h2, h3));
    *(uint2*)(lo + off) = make_uint2(bf2u(l0, l1), bf2u(l2, l3));
}

__device__ __forceinline__ float gelu_tanh(float v) {
    const float c = 0.7978845608028654f;
    float u = c * (v + 0.044715f * v * v * v);
    return 0.5f * v * (1.0f + tanhf(u));
}

// ---------------------------------------------------------------------------
// Weight transpose + split: W[K][N] -> hi/lo[N][K] bf16
// ---------------------------------------------------------------------------
__global__ __launch_bounds__(256) void wsplit_t(
    const float* __restrict__ W, __nv_bfloat16* __restrict__ hi,
    __nv_bfloat16* __restrict__ lo, int K, int N)
{
    __shared__ float t[32][33];
    const int n0 = blockIdx.x * 32, k0 = blockIdx.y * 32;
    const int tx = threadIdx.x, ty = threadIdx.y;
    #pragma unroll
    for (int i = ty; i < 32; i += 8)
        t[i][tx] = W[(size_t)(k0 + i) * N + n0 + tx];
    __syncthreads();
    #pragma unroll
    for (int i = ty; i < 32; i += 8) {
        const float v = t[tx][i];
        const __nv_bfloat16 h = __float2bfloat16(v);
        const __nv_bfloat16 l = __float2bfloat16(v - __bfloat162float(h));
        const size_t o = (size_t)(n0 + i) * K + k0 + tx;
        hi[o] = h; lo[o] = l;
    }
}

// ---------------------------------------------------------------------------
// LayerNorm -> bf16 hi/lo
// ---------------------------------------------------------------------------
__global__ __launch_bounds__(256) void layernorm_k(
    const float* __restrict__ x, const float* __restrict__ gamma,
    const float* __restrict__ beta,
    __nv_bfloat16* __restrict__ ohi, __nv_bfloat16* __restrict__ olo)
{
    const int row = blockIdx.x;
    const int t = threadIdx.x;
    const float4 v = *(const float4*)(x + (size_t)row * D_ + t * 4);

    float s = v.x + v.y + v.z + v.w;
    float q = v.x * v.x + v.y * v.y + v.z * v.z + v.w * v.w;
    #pragma unroll
    for (int off = 16; off > 0; off >>= 1) {
        s += __shfl_down_sync(0xffffffffu, s, off);
        q += __shfl_down_sync(0xffffffffu, q, off);
    }
    __shared__ float ss[8], qq[8];
    const int wid = t >> 5, lane = t & 31;
    if (lane == 0) { ss[wid] = s; qq[wid] = q; }
    __syncthreads();
    if (t == 0) {
        float S = 0.f, Q = 0.f;
        #pragma unroll
        for (int i = 0; i < 8; i++) { S += ss[i]; Q += qq[i]; }
        ss[0] = S; qq[0] = Q;
    }
    __syncthreads();
    const float mu = ss[0] * (1.0f / D_);
    const float var = qq[0] * (1.0f / D_) - mu * mu;
    const float rstd = rsqrtf(var + LN_EPS);

    const float4 g4 = *(const float4*)(gamma + t * 4);
    const float4 b4 = *(const float4*)(beta + t * 4);
    const float ox = (v.x - mu) * rstd * g4.x + b4.x;
    const float oy = (v.y - mu) * rstd * g4.y + b4.y;
    const float oz = (v.z - mu) * rstd * g4.z + b4.z;
    const float ow = (v.w - mu) * rstd * g4.w + b4.w;
    split_store4(ohi, olo, (size_t)row * D_ + t * 4, ox, oy, oz, ow);
}

// ---------------------------------------------------------------------------
// WMMA GEMM: bf16x3, 128x256 tile, 3-stage cp.async (unchanged, proven).
// EPI: 0 = fp32 out, 1 = +bias +residual -> fp32,
//      2 = +bias +gelu -> bf16 hi/lo, 3 = split -> bf16 hi/lo (no bias)
// ---------------------------------------------------------------------------
#define BM 128
#define BN 256
#define BK 32
#define NSTAGE 3
#define LDS_ 40
#define A_EL (128 * LDS_)
#define B_EL (256 * LDS_)
#define STAGE_EL (2 * A_EL + 2 * B_EL)
#define EPI_LD 260
#define GEMM_SMEM (NSTAGE * STAGE_EL * 2)

template <int EPI>
__global__ __launch_bounds__(256, 1) void wm_gemm(
    const __nv_bfloat16* __restrict__ Ahi, const __nv_bfloat16* __restrict__ Alo,
    const __nv_bfloat16* __restrict__ Bhi, const __nv_bfloat16* __restrict__ Blo,
    const float* __restrict__ bias, const float* __restrict__ res,
    float* __restrict__ C, __nv_bfloat16* __restrict__ Chi,
    __nv_bfloat16* __restrict__ Clo, int M, int N, int K)
{
    extern __shared__ char smem[];
    __nv_bfloat16* sb = (__nv_bfloat16*)smem;
    const uint32_t sbase = smem_to_u32(smem);
    const int tid = threadIdx.x;
    const int w = tid >> 5;
    const int wm = w >> 2;
    const int wn = w & 3;
    const int mBase = blockIdx.y * BM;
    const int nBase = blockIdx.x * BN;

    const __nv_bfloat16* gsrc[4] = {
        Ahi + (size_t)mBase * K,
        Alo + (size_t)mBase * K,
        Bhi + (size_t)nBase * K,
        Blo + (size_t)nBase * K };
    const int unit_of_it[12]  = {0,0, 1,1, 2,2,2,2, 3,3,3,3};
    const int rbase_of_it[12] = {0,0, 128,128, 256,256,256,256, 512,512,512,512};
    const int soff_of_unit[4] = {0, A_EL, 2 * A_EL, 2 * A_EL + B_EL};

    wmma::fragment<wmma::accumulator, 16, 16, 16, float> acc[4][4];
    #pragma unroll
    for (int i = 0; i < 4; i++)
        #pragma unroll
        for (int j = 0; j < 4; j++)
            wmma::fill_fragment(acc[i][j], 0.0f);

    const int nchunks = K / BK;

    auto load_stage = [&](int stg, int k0) {
        const uint32_t so = sbase + (uint32_t)stg * STAGE_EL * 2;
        #pragma unroll
        for (int it = 0; it < 12; it++) {
            const int idx = it * 256 + tid;
            const int r = idx >> 2;
            const int seg = idx & 3;
            const int u = unit_of_it[it];
            const int lr = r - rbase_of_it[it];
            cp16(so + (uint32_t)(soff_of_unit[u] + lr * LDS_ + seg * 8) * 2,
                 gsrc[u] + (size_t)lr * K + k0 + seg * 8);
        }
    };

    load_stage(0, 0);
    CP_COMMIT();
    load_stage(1, BK);
    CP_COMMIT();

    int s = 0, sl = 2;
    for (int c = 0; c < nchunks; c++) {
        cp_wait_group<1>();
        __syncthreads();
        if (c + 2 < nchunks) {
            load_stage(sl, (c + 2) * BK);
            CP_COMMIT();
        }
        const __nv_bfloat16* st = sb + s * STAGE_EL;
        const __nv_bfloat16* sAh = st;
        const __nv_bfloat16* sAl = st + A_EL;
        const __nv_bfloat16* sBh = st + 2 * A_EL;
        const __nv_bfloat16* sBl = st + 2 * A_EL + B_EL;

        #pragma unroll
        for (int kk = 0; kk < BK; kk += 16) {
            wmma::fragment<wmma::matrix_b, 16, 16, 16, __nv_bfloat16,
                           wmma::col_major> bh[4], bl[4];
            #pragma unroll
            for (int j = 0; j < 4; j++) {
                wmma::load_matrix_sync(bh[j],
                    sBh + (wn * 64 + j * 16) * LDS_ + kk, LDS_);
                wmma::load_matrix_sync(bl[j],
                    sBl + (wn * 64 + j * 16) * LDS_ + kk, LDS_);
            }
            #pragma unroll
            for (int i = 0; i < 4; i++) {
                wmma::fragment<wmma::matrix_a, 16, 16, 16, __nv_bfloat16,
                               wmma::row_major> ah, al;
                wmma::load_matrix_sync(ah,
                    sAh + (wm * 64 + i * 16) * LDS_ + kk, LDS_);
                wmma::load_matrix_sync(al,
                    sAl + (wm * 64 + i * 16) * LDS_ + kk, LDS_);
                #pragma unroll
                for (int j = 0; j < 4; j++) {
                    wmma::mma_sync(acc[i][j], ah, bh[j], acc[i][j]);
                    wmma::mma_sync(acc[i][j], ah, bl[j], acc[i][j]);
                    wmma::mma_sync(acc[i][j], al, bh[j], acc[i][j]);
                }
            }
        }
        s = (s == NSTAGE - 1) ? 0 : s + 1;
        sl = (sl == NSTAGE - 1) ? 0 : sl + 1;
    }

    __syncthreads();
    float* sf = (float*)smem;
    #pragma unroll
    for (int i = 0; i < 4; i++)
        #pragma unroll
        for (int j = 0; j < 4; j++)
            wmma::store_matrix_sync(
                sf + (wm * 64 + i * 16) * EPI_LD + wn * 64 + j * 16,
                acc[i][j], EPI_LD, wmma::mem_row_major);
    __syncthreads();

    #pragma unroll 4
    for (int it = 0; it < 32; it++) {
        const int idx = tid + it * 256;
        const int rr = idx >> 6;
        const int c4 = (idx & 63) * 4;
        float4 v = *(const float4*)&sf[rr * EPI_LD + c4];
        const int m = mBase + rr;
        const int n = nBase + c4;
        if (EPI == 1 || EPI == 2) {
            const float4 bi = *(const float4*)(bias + n);
            v.x += bi.x; v.y += bi.y; v.z += bi.z; v.w += bi.w;
        }
        if (EPI == 2) {
            v.x = gelu_tanh(v.x); v.y = gelu_tanh(v.y);
            v.z = gelu_tanh(v.z); v.w = gelu_tanh(v.w);
            split_store4(Chi, Clo, (size_t)m * N + n, v.x, v.y, v.z, v.w);
        } else if (EPI == 3) {
            split_store4(Chi, Clo, (size_t)m * N + n, v.x, v.y, v.z, v.w);
        } else {
            if (EPI == 1) {
                const float4 rv = *(const float4*)(res + (size_t)m * N + n);
                v.x += rv.x; v.y += rv.y; v.z += rv.z; v.w += rv.w;
            }
            *(float4*)(C + (size_t)m * N + n) = v;
        }
    }
}

// ---------------------------------------------------------------------------
// WMMA flash attention (R10 shape: Q=64, KV=64, 128 threads, 109 KB smem)
// + liveness-split KV prefetch: K(i+1) issued after the S barrier (K dead),
// V(i+1) issued after the PV barrier (V dead). No extra smem, no extra syncs.
// ---------------------------------------------------------------------------
#define FQ_LD 72                         // bf16 ld, 144B rows
#define FS_LD 68                         // fp32 ld, 272B rows
#define OFF_QH 0
#define OFF_QL 9216
#define OFF_KH 18432
#define OFF_KL 27648
#define OFF_VH 36864
#define OFF_VL 46080
#define OFF_PH 55296
#define OFF_PL 64512
#define OFF_S  73728
#define OFF_O  91136
#define OFF_M  108544
#define OFF_L  108800
#define OFF_C  109056
#define FAW_SMEM 109312

__global__ __launch_bounds__(128) void flash_attn_w(
    const __nv_bfloat16* __restrict__ qkvh,
    const __nv_bfloat16* __restrict__ qkvl,
    __nv_bfloat16* __restrict__ ohi, __nv_bfloat16* __restrict__ olo)
{
    extern __shared__ char sm8[];
    __nv_bfloat16* sQh = (__nv_bfloat16*)(sm8 + OFF_QH);
    __nv_bfloat16* sQl = (__nv_bfloat16*)(sm8 + OFF_QL);
    __nv_bfloat16* sKh = (__nv_bfloat16*)(sm8 + OFF_KH);
    __nv_bfloat16* sKl = (__nv_bfloat16*)(sm8 + OFF_KL);
    __nv_bfloat16* sVh = (__nv_bfloat16*)(sm8 + OFF_VH);
    __nv_bfloat16* sVl = (__nv_bfloat16*)(sm8 + OFF_VL);
    __nv_bfloat16* sPh = (__nv_bfloat16*)(sm8 + OFF_PH);
    __nv_bfloat16* sPl = (__nv_bfloat16*)(sm8 + OFF_PL);
    float* sS    = (float*)(sm8 + OFF_S);
    float* sO    = (float*)(sm8 + OFF_O);
    float* mrun  = (float*)(sm8 + OFF_M);
    float* lrun  = (float*)(sm8 + OFF_L);
    float* corrA = (float*)(sm8 + OFF_C);

    const int b = blockIdx.z, h = blockIdx.y;
    const int qb = blockIdx.x * 64;
    const int tid = threadIdx.x;
    const int w = tid >> 5;
    const int wm2 = w >> 1, wn2 = w & 1;
    const uint32_t sbase = smem_to_u32(sm8);

    // K loader (hi+lo) and V loader (hi+lo): 8 cp16 per thread each
    auto load_k = [&](int kb) {
        const size_t koff = (size_t)(b * L_ + kb) * (3 * D_) + D_ + h * HD_;
        #pragma unroll
        for (int it = 0; it < 4; it++) {
            const int i = it * 128 + tid;
            const int rr = i >> 3, seg = i & 7;
            const uint32_t so = (uint32_t)(rr * FQ_LD + seg * 8) * 2;
            const size_t g = koff + (size_t)rr * (3 * D_) + seg * 8;
            cp16(sbase + OFF_KH + so, qkvh + g);
            cp16(sbase + OFF_KL + so, qkvl + g);
        }
        CP_COMMIT();
    };
    auto load_v = [&](int kb) {
        const size_t voff = (size_t)(b * L_ + kb) * (3 * D_) + 2 * D_ + h * HD_;
        #pragma unroll
        for (int it = 0; it < 4; it++) {
            const int i = it * 128 + tid;
            const int rr = i >> 3, seg = i & 7;
            const uint32_t so = (uint32_t)(rr * FQ_LD + seg * 8) * 2;
            const size_t g = voff + (size_t)rr * (3 * D_) + seg * 8;
            cp16(sbase + OFF_VH + so, qkvh + g);
            cp16(sbase + OFF_VL + so, qkvl + g);
        }
        CP_COMMIT();
    };

    // async-load Q hi/lo tiles (64 x 64 bf16 each)
    {
        const size_t qoff = (size_t)(b * L_ + qb) * (3 * D_) + h * HD_;
        #pragma unroll
        for (int it = 0; it < 4; it++) {
            const int i = it * 128 + tid;
            const int rr = i >> 3, seg = i & 7;
            const uint32_t so = (uint32_t)(rr * FQ_LD + seg * 8) * 2;
            const size_t g = qoff + (size_t)rr * (3 * D_) + seg * 8;
            cp16(sbase + OFF_QH + so, qkvh + g);
            cp16(sbase + OFF_QL + so, qkvl + g);
        }
        CP_COMMIT();
    }
    load_k(0);
    load_v(0);
    // zero O, init stats (overlaps the async loads)
    for (int i = tid; i < 64 * FS_LD; i += 128) sO[i] = 0.0f;
    if (tid < 64) { mrun[tid] = -INFINITY; lrun[tid] = 0.0f; }
    cp_wait_group<0>();
    __syncthreads();

    const int r = tid >> 1;          // softmax row 0..63
    const int hf = tid & 1;          // column half

    for (int kb = 0; kb < L_; kb += 64) {
        // ---- S = Q K^T (bf16x3) ----
        {
            wmma::fragment<wmma::accumulator, 16, 16, 16, float> sa[2][2];
            #pragma unroll
            for (int i = 0; i < 2; i++)
                #pragma unroll
                for (int j = 0; j < 2; j++) wmma::fill_fragment(sa[i][j], 0.0f);
            #pragma unroll
            for (int d = 0; d < HD_; d += 16) {
                wmma::fragment<wmma::matrix_b, 16, 16, 16, __nv_bfloat16,
                               wmma::col_major> bh[2], bl[2];
                #pragma unroll
                for (int j = 0; j < 2; j++) {
                    wmma::load_matrix_sync(bh[j],
                        sKh + (wn2 * 32 + j * 16) * FQ_LD + d, FQ_LD);
                    wmma::load_matrix_sync(bl[j],
                        sKl + (wn2 * 32 + j * 16) * FQ_LD + d, FQ_LD);
                }
                #pragma unroll
                for (int i = 0; i < 2; i++) {
                    wmma::fragment<wmma::matrix_a, 16, 16, 16, __nv_bfloat16,
                                   wmma::row_major> ah, al;
                    wmma::load_matrix_sync(ah,
                        sQh + (wm2 * 32 + i * 16) * FQ_LD + d, FQ_LD);
                    wmma::load_matrix_sync(al,
                        sQl + (wm2 * 32 + i * 16) * FQ_LD + d, FQ_LD);
                    #pragma unroll
                    for (int j = 0; j < 2; j++) {
                        wmma::mma_sync(sa[i][j], ah, bh[j], sa[i][j]);
                        wmma::mma_sync(sa[i][j], ah, bl[j], sa[i][j]);
                        wmma::mma_sync(sa[i][j], al, bh[j], sa[i][j]);
                    }
                }
            }
            #pragma unroll
            for (int i = 0; i < 2; i++)
                #pragma unroll
                for (int j = 0; j < 2; j++)
                    wmma::store_matrix_sync(
                        sS + (wm2 * 32 + i * 16) * FS_LD + wn2 * 32 + j * 16,
                        sa[i][j], FS_LD, wmma::mem_row_major);
        }
        __syncthreads();

        // K buffer is dead now — prefetch next K (overlaps softmax + PV)
        if (kb + 64 < L_) load_k(kb + 64);

        // ---- online softmax (2 threads/row, 32 cols each) ----
        {
            float sv[32];
            float tmax = -INFINITY;
            #pragma unroll
            for (int g = 0; g < 8; g++) {
                const float4 f = *(const float4*)&sS[r * FS_LD + hf * 32 + g * 4];
                sv[g * 4 + 0] = f.x * 0.125f; sv[g * 4 + 1] = f.y * 0.125f;
                sv[g * 4 + 2] = f.z * 0.125f; sv[g * 4 + 3] = f.w * 0.125f;
                tmax = fmaxf(tmax, fmaxf(fmaxf(sv[g*4], sv[g*4+1]),
                                         fmaxf(sv[g*4+2], sv[g*4+3])));
            }
            tmax = fmaxf(tmax, __shfl_xor_sync(0xffffffffu, tmax, 1));
            const float mold = mrun[r];
            const float mnew = fmaxf(mold, tmax);
            const float corr = __expf(mold - mnew);
            float rsum = 0.f;
            #pragma unroll
            for (int g = 0; g < 8; g++) {
                const float p0 = __expf(sv[g*4+0] - mnew);
                const float p1 = __expf(sv[g*4+1] - mnew);
                const float p2 = __expf(sv[g*4+2] - mnew);
                const float p3 = __expf(sv[g*4+3] - mnew);
                rsum += (p0 + p1) + (p2 + p3);
                split_store4(sPh, sPl, (size_t)r * FQ_LD + hf * 32 + g * 4,
                             p0, p1, p2, p3);
            }
            rsum += __shfl_xor_sync(0xffffffffu, rsum, 1);
            if (hf == 0) {
                lrun[r] = lrun[r] * corr + rsum;
                mrun[r] = mnew;
                corrA[r] = corr;
            }
        }
        __syncthreads();

        // ---- Od = P V (bf16x3), into sS ----
        {
            wmma::fragment<wmma::accumulator, 16, 16, 16, float> oa[2][2];
            #pragma unroll
            for (int i = 0; i < 2; i++)
                #pragma unroll
                for (int j = 0; j < 2; j++) wmma::fill_fragment(oa[i][j], 0.0f);
            #pragma unroll
            for (int kk = 0; kk < 64; kk += 16) {
                wmma::fragment<wmma::matrix_b, 16, 16, 16, __nv_bfloat16,
                               wmma::row_major> bh[2], bl[2];
                #pragma unroll
                for (int j = 0; j < 2; j++) {
                    wmma::load_matrix_sync(bh[j],
                        sVh + kk * FQ_LD + wn2 * 32 + j * 16, FQ_LD);
                    wmma::load_matrix_sync(bl[j],
                        sVl + kk * FQ_LD + wn2 * 32 + j * 16, FQ_LD);
                }
                #pragma unroll
                for (int i = 0; i < 2; i++) {
                    wmma::fragment<wmma::matrix_a, 16, 16, 16, __nv_bfloat16,
                                   wmma::row_major> ah, al;
                    wmma::load_matrix_sync(ah,
                        sPh + (wm2 * 32 + i * 16) * FQ_LD + kk, FQ_LD);
                    wmma::load_matrix_sync(al,
                        sPl + (wm2 * 32 + i * 16) * FQ_LD + kk, FQ_LD);
                    #pragma unroll
                    for (int j = 0; j < 2; j++) {
                        wmma::mma_sync(oa[i][j], ah, bh[j], oa[i][j]);
                        wmma::mma_sync(oa[i][j], ah, bl[j], oa[i][j]);
                        wmma::mma_sync(oa[i][j], al, bh[j], oa[i][j]);
                    }
                }
            }
            #pragma unroll
            for (int i = 0; i < 2; i++)
                #pragma unroll
                for (int j = 0; j < 2; j++)
                    wmma::store_matrix_sync(
                        sS + (wm2 * 32 + i * 16) * FS_LD + wn2 * 32 + j * 16,
                        oa[i][j], FS_LD, wmma::mem_row_major);
        }
        __syncthreads();

        // V buffer is dead now — prefetch next V (overlaps O-update)
        if (kb + 64 < L_) load_v(kb + 64);

        // ---- O = O * corr + Od ----
        {
            const float corr = corrA[r];
            #pragma unroll
            for (int g = 0; g < 8; g++) {
                const int o = r * FS_LD + hf * 32 + g * 4;
                float4 ov = *(const float4*)&sO[o];
                const float4 dv = *(const float4*)&sS[o];
                ov.x = ov.x * corr + dv.x; ov.y = ov.y * corr + dv.y;
                ov.z = ov.z * corr + dv.z; ov.w = ov.w * corr + dv.w;
                *(float4*)&sO[o] = ov;
            }
        }
        cp_wait_group<0>();
        __syncthreads();
    }

    // normalize + split-store
    {
        const float inv = 1.0f / lrun[r];
        #pragma unroll
        for (int g = 0; g < 8; g++) {
            const float4 ov = *(const float4*)&sO[r * FS_LD + hf * 32 + g * 4];
            split_store4(ohi, olo,
                (size_t)(b * L_ + qb + r) * D_ + h * HD_ + hf * 32 + g * 4,
                ov.x * inv, ov.y * inv, ov.z * inv, ov.w * inv);
        }
    }
}

// ---------------------------------------------------------------------------
// Launch
// ---------------------------------------------------------------------------
extern "C" void kernel_launch(void* const* d_in, const int* in_sizes, int n_in,
                              void* d_out, int out_size)
{
    const float* x      = (const float*)d_in[0];
    const float* ln1_s  = (const float*)d_in[1];
    const float* ln1_b  = (const float*)d_in[2];
    const float* w_qkv  = (const float*)d_in[3];
    const float* w_proj = (const float*)d_in[4];
    const float* b_proj = (const float*)d_in[5];
    const float* ln2_s  = (const float*)d_in[6];
    const float* ln2_b  = (const float*)d_in[7];
    const float* w_mlp1 = (const float*)d_in[8];
    const float* b_mlp1 = (const float*)d_in[9];
    const float* w_mlp2 = (const float*)d_in[10];
    const float* b_mlp2 = (const float*)d_in[11];
    float* out = (float*)d_out;

    __nv_bfloat16 *hhi, *hlo, *qkvh, *qkvl, *athi, *atlo, *midhi, *midlo;
    __nv_bfloat16 *wqh, *wql, *wph, *wpl, *w1h, *w1l, *w2h, *w2l;
    float *x1;
    cudaGetSymbolAddress((void**)&hhi, g_h_hi);
    cudaGetSymbolAddress((void**)&hlo, g_h_lo);
    cudaGetSymbolAddress((void**)&qkvh, g_qkv_hi);
    cudaGetSymbolAddress((void**)&qkvl, g_qkv_lo);
    cudaGetSymbolAddress((void**)&athi, g_at_hi);
    cudaGetSymbolAddress((void**)&atlo, g_at_lo);
    cudaGetSymbolAddress((void**)&x1, g_x1);
    cudaGetSymbolAddress((void**)&midhi, g_mid_hi);
    cudaGetSymbolAddress((void**)&midlo, g_mid_lo);
    cudaGetSymbolAddress((void**)&wqh, g_wqkv_hi);
    cudaGetSymbolAddress((void**)&wql, g_wqkv_lo);
    cudaGetSymbolAddress((void**)&wph, g_wpr_hi);
    cudaGetSymbolAddress((void**)&wpl, g_wpr_lo);
    cudaGetSymbolAddress((void**)&w1h, g_wm1_hi);
    cudaGetSymbolAddress((void**)&w1l, g_wm1_lo);
    cudaGetSymbolAddress((void**)&w2h, g_wm2_hi);
    cudaGetSymbolAddress((void**)&w2l, g_wm2_lo);

    static bool attr_set = false;
    if (!attr_set) {
        cudaFuncSetAttribute(flash_attn_w,
            cudaFuncAttributeMaxDynamicSharedMemorySize, FAW_SMEM);
        cudaFuncSetAttribute(wm_gemm<1>,
            cudaFuncAttributeMaxDynamicSharedMemorySize, GEMM_SMEM);
        cudaFuncSetAttribute(wm_gemm<2>,
            cudaFuncAttributeMaxDynamicSharedMemorySize, GEMM_SMEM);
        cudaFuncSetAttribute(wm_gemm<3>,
            cudaFuncAttributeMaxDynamicSharedMemorySize, GEMM_SMEM);
        attr_set = true;
    }

    const dim3 tb(32, 8);
    wsplit_t<<<dim3(3 * D_ / 32, D_ / 32), tb>>>(w_qkv, wqh, wql, D_, 3 * D_);
    wsplit_t<<<dim3(D_ / 32, D_ / 32), tb>>>(w_proj, wph, wpl, D_, D_);
    wsplit_t<<<dim3(F_ / 32, D_ / 32), tb>>>(w_mlp1, w1h, w1l, D_, F_);
    wsplit_t<<<dim3(D_ / 32, F_ / 32), tb>>>(w_mlp2, w2h, w2l, F_, D_);

    // 1) pre-norm 1 -> bf16 hi/lo
    layernorm_k<<<M_, 256>>>(x, ln1_s, ln1_b, hhi, hlo);
    // 2) qkv projection -> bf16 hi/lo directly
    wm_gemm<3><<<dim3(3 * D_ / BN, M_ / BM), 256, GEMM_SMEM>>>(
        hhi, hlo, wqh, wql, nullptr, nullptr, nullptr, qkvh, qkvl,
        M_, 3 * D_, D_);
    // 3) attention (wmma bf16x3, liveness-split KV prefetch) -> bf16 hi/lo
    flash_attn_w<<<dim3(L_ / 64, H_, B_), 128, FAW_SMEM>>>(
        qkvh, qkvl, athi, atlo);
    // 4) out proj + bias + residual -> fp32 x1
    wm_gemm<1><<<dim3(D_ / BN, M_ / BM), 256, GEMM_SMEM>>>(
        athi, atlo, wph, wpl, b_proj, x, x1, nullptr, nullptr,
        M_, D_, D_);
    // 5) pre-norm 2 -> bf16 hi/lo
    layernorm_k<<<M_, 256>>>(x1, ln2_s, ln2_b, hhi, hlo);
    // 6) MLP up + bias + gelu -> bf16 hi/lo
    wm_gemm<2><<<dim3(F_ / BN, M_ / BM), 256, GEMM_SMEM>>>(
        hhi, hlo, w1h, w1l, b_mlp1, nullptr, nullptr, midhi, midlo,
        M_, F_, D_);
    // 7) MLP down + bias + residual -> final out
    wm_gemm<1><<<dim3(D_ / BN, M_ / BM), 256, GEMM_SMEM>>>(
        midhi, midlo, w2h, w2l, b_mlp2, x1, out, nullptr, nullptr,
        M_, D_, F_);
}

// round 14
// speedup vs baseline: 1.1230x; 1.0571x over previous
#include <cuda_runtime.h>
#include <cuda_bf16.h>
#include <mma.h>
#include <math.h>
#include <stdint.h>

using namespace nvcuda;

// Problem constants
#define B_ 2
#define L_ 2048
#define D_ 1024
#define F_ 4096
#define H_ 16
#define HD_ 64
#define M_ (B_ * L_)
#define LN_EPS 1e-6f

// ---------------------------------------------------------------------------
// Scratch (static device globals; no allocation anywhere)
// ---------------------------------------------------------------------------
__device__ __nv_bfloat16 g_h_hi[M_ * D_];
__device__ __nv_bfloat16 g_h_lo[M_ * D_];
__device__ __nv_bfloat16 g_qkv_hi[M_ * 3 * D_];
__device__ __nv_bfloat16 g_qkv_lo[M_ * 3 * D_];
__device__ __nv_bfloat16 g_at_hi[M_ * D_];
__device__ __nv_bfloat16 g_at_lo[M_ * D_];
__device__ float         g_x1[M_ * D_];
__device__ __nv_bfloat16 g_mid_hi[M_ * F_];
__device__ __nv_bfloat16 g_mid_lo[M_ * F_];
// weights transposed to [N][K], split hi/lo
__device__ __nv_bfloat16 g_wqkv_hi[3 * D_ * D_];
__device__ __nv_bfloat16 g_wqkv_lo[3 * D_ * D_];
__device__ __nv_bfloat16 g_wpr_hi[D_ * D_];
__device__ __nv_bfloat16 g_wpr_lo[D_ * D_];
__device__ __nv_bfloat16 g_wm1_hi[F_ * D_];
__device__ __nv_bfloat16 g_wm1_lo[F_ * D_];
__device__ __nv_bfloat16 g_wm2_hi[D_ * F_];
__device__ __nv_bfloat16 g_wm2_lo[D_ * F_];

// ---------------------------------------------------------------------------
// helpers
// ---------------------------------------------------------------------------
__device__ __forceinline__ uint32_t smem_to_u32(const void* p) {
    uint32_t a;
    asm("{ .reg .u64 t; cvta.to.shared.u64 t, %1; cvt.u32.u64 %0, t; }"
        : "=r"(a) : "l"(p));
    return a;
}

__device__ __forceinline__ void cp16(uint32_t daddr, const void* g) {
    asm volatile("cp.async.cg.shared.global [%0], [%1], 16;"
                 :: "r"(daddr), "l"(g));
}
#define CP_COMMIT() asm volatile("cp.async.commit_group;" ::: "memory")
template <int N>
__device__ __forceinline__ void cp_wait_group() {
    asm volatile("cp.async.wait_group %0;" :: "n"(N) : "memory");
}

__device__ __forceinline__ uint32_t bf2u(__nv_bfloat16 a, __nv_bfloat16 b) {
    return (uint32_t)__bfloat16_as_ushort(a) |
           ((uint32_t)__bfloat16_as_ushort(b) << 16);
}

__device__ __forceinline__ void split_store4(
    __nv_bfloat16* __restrict__ hi, __nv_bfloat16* __restrict__ lo,
    size_t off, float a, float b, float c, float d)
{
    __nv_bfloat16 h0 = __float2bfloat16(a), h1 = __float2bfloat16(b);
    __nv_bfloat16 h2 = __float2bfloat16(c), h3 = __float2bfloat16(d);
    __nv_bfloat16 l0 = __float2bfloat16(a - __bfloat162float(h0));
    __nv_bfloat16 l1 = __float2bfloat16(b - __bfloat162float(h1));
    __nv_bfloat16 l2 = __float2bfloat16(c - __bfloat162float(h2));
    __nv_bfloat16 l3 = __float2bfloat16(d - __bfloat162float(h3));
    *(uint2*)(hi + off) = make_uint2(bf2u(h0, h1), bf2u(h2, h3));
    *(uint2*)(lo + off) = make_uint2(bf2u(l0, l1), bf2u(l2, l3));
}

__device__ __forceinline__ float gelu_tanh(float v) {
    const float c = 0.7978845608028654f;
    float u = c * (v + 0.044715f * v * v * v);
    return 0.5f * v * (1.0f + tanhf(u));
}

// ---------------------------------------------------------------------------
// Weight transpose + split: W[K][N] -> hi/lo[N][K] bf16
// ---------------------------------------------------------------------------
__global__ __launch_bounds__(256) void wsplit_t(
    const float* __restrict__ W, __nv_bfloat16* __restrict__ hi,
    __nv_bfloat16* __restrict__ lo, int K, int N)
{
    __shared__ float t[32][33];
    const int n0 = blockIdx.x * 32, k0 = blockIdx.y * 32;
    const int tx = threadIdx.x, ty = threadIdx.y;
    #pragma unroll
    for (int i = ty; i < 32; i += 8)
        t[i][tx] = W[(size_t)(k0 + i) * N + n0 + tx];
    __syncthreads();
    #pragma unroll
    for (int i = ty; i < 32; i += 8) {
        const float v = t[tx][i];
        const __nv_bfloat16 h = __float2bfloat16(v);
        const __nv_bfloat16 l = __float2bfloat16(v - __bfloat162float(h));
        const size_t o = (size_t)(n0 + i) * K + k0 + tx;
        hi[o] = h; lo[o] = l;
    }
}

// ---------------------------------------------------------------------------
// LayerNorm -> bf16 hi/lo
// ---------------------------------------------------------------------------
__global__ __launch_bounds__(256) void layernorm_k(
    const float* __restrict__ x, const float* __restrict__ gamma,
    const float* __restrict__ beta,
    __nv_bfloat16* __restrict__ ohi, __nv_bfloat16* __restrict__ olo)
{
    const int row = blockIdx.x;
    const int t = threadIdx.x;
    const float4 v = *(const float4*)(x + (size_t)row * D_ + t * 4);

    float s = v.x + v.y + v.z + v.w;
    float q = v.x * v.x + v.y * v.y + v.z * v.z + v.w * v.w;
    #pragma unroll
    for (int off = 16; off > 0; off >>= 1) {
        s += __shfl_down_sync(0xffffffffu, s, off);
        q += __shfl_down_sync(0xffffffffu, q, off);
    }
    __shared__ float ss[8], qq[8];
    const int wid = t >> 5, lane = t & 31;
    if (lane == 0) { ss[wid] = s; qq[wid] = q; }
    __syncthreads();
    if (t == 0) {
        float S = 0.f, Q = 0.f;
        #pragma unroll
        for (int i = 0; i < 8; i++) { S += ss[i]; Q += qq[i]; }
        ss[0] = S; qq[0] = Q;
    }
    __syncthreads();
    const float mu = ss[0] * (1.0f / D_);
    const float var = qq[0] * (1.0f / D_) - mu * mu;
    const float rstd = rsqrtf(var + LN_EPS);

    const float4 g4 = *(const float4*)(gamma + t * 4);
    const float4 b4 = *(const float4*)(beta + t * 4);
    const float ox = (v.x - mu) * rstd * g4.x + b4.x;
    const float oy = (v.y - mu) * rstd * g4.y + b4.y;
    const float oz = (v.z - mu) * rstd * g4.z + b4.z;
    const float ow = (v.w - mu) * rstd * g4.w + b4.w;
    split_store4(ohi, olo, (size_t)row * D_ + t * 4, ox, oy, oz, ow);
}

// ---------------------------------------------------------------------------
// WMMA GEMM: bf16x3, 128x256 tile, 3-stage cp.async (unchanged, proven).
// EPI: 0 = fp32 out, 1 = +bias +residual -> fp32,
//      2 = +bias +gelu -> bf16 hi/lo, 3 = split -> bf16 hi/lo (no bias)
// ---------------------------------------------------------------------------
#define BM 128
#define BN 256
#define BK 32
#define NSTAGE 3
#define LDS_ 40
#define A_EL (128 * LDS_)
#define B_EL (256 * LDS_)
#define STAGE_EL (2 * A_EL + 2 * B_EL)
#define EPI_LD 260
#define GEMM_SMEM (NSTAGE * STAGE_EL * 2)

template <int EPI>
__global__ __launch_bounds__(256, 1) void wm_gemm(
    const __nv_bfloat16* __restrict__ Ahi, const __nv_bfloat16* __restrict__ Alo,
    const __nv_bfloat16* __restrict__ Bhi, const __nv_bfloat16* __restrict__ Blo,
    const float* __restrict__ bias, const float* __restrict__ res,
    float* __restrict__ C, __nv_bfloat16* __restrict__ Chi,
    __nv_bfloat16* __restrict__ Clo, int M, int N, int K)
{
    extern __shared__ char smem[];
    __nv_bfloat16* sb = (__nv_bfloat16*)smem;
    const uint32_t sbase = smem_to_u32(smem);
    const int tid = threadIdx.x;
    const int w = tid >> 5;
    const int wm = w >> 2;
    const int wn = w & 3;
    const int mBase = blockIdx.y * BM;
    const int nBase = blockIdx.x * BN;

    const __nv_bfloat16* gsrc[4] = {
        Ahi + (size_t)mBase * K,
        Alo + (size_t)mBase * K,
        Bhi + (size_t)nBase * K,
        Blo + (size_t)nBase * K };
    const int unit_of_it[12]  = {0,0, 1,1, 2,2,2,2, 3,3,3,3};
    const int rbase_of_it[12] = {0,0, 128,128, 256,256,256,256, 512,512,512,512};
    const int soff_of_unit[4] = {0, A_EL, 2 * A_EL, 2 * A_EL + B_EL};

    wmma::fragment<wmma::accumulator, 16, 16, 16, float> acc[4][4];
    #pragma unroll
    for (int i = 0; i < 4; i++)
        #pragma unroll
        for (int j = 0; j < 4; j++)
            wmma::fill_fragment(acc[i][j], 0.0f);

    const int nchunks = K / BK;

    auto load_stage = [&](int stg, int k0) {
        const uint32_t so = sbase + (uint32_t)stg * STAGE_EL * 2;
        #pragma unroll
        for (int it = 0; it < 12; it++) {
            const int idx = it * 256 + tid;
            const int r = idx >> 2;
            const int seg = idx & 3;
            const int u = unit_of_it[it];
            const int lr = r - rbase_of_it[it];
            cp16(so + (uint32_t)(soff_of_unit[u] + lr * LDS_ + seg * 8) * 2,
                 gsrc[u] + (size_t)lr * K + k0 + seg * 8);
        }
    };

    load_stage(0, 0);
    CP_COMMIT();
    load_stage(1, BK);
    CP_COMMIT();

    int s = 0, sl = 2;
    for (int c = 0; c < nchunks; c++) {
        cp_wait_group<1>();
        __syncthreads();
        if (c + 2 < nchunks) {
            load_stage(sl, (c + 2) * BK);
            CP_COMMIT();
        }
        const __nv_bfloat16* st = sb + s * STAGE_EL;
        const __nv_bfloat16* sAh = st;
        const __nv_bfloat16* sAl = st + A_EL;
        const __nv_bfloat16* sBh = st + 2 * A_EL;
        const __nv_bfloat16* sBl = st + 2 * A_EL + B_EL;

        #pragma unroll
        for (int kk = 0; kk < BK; kk += 16) {
            wmma::fragment<wmma::matrix_b, 16, 16, 16, __nv_bfloat16,
                           wmma::col_major> bh[4], bl[4];
            #pragma unroll
            for (int j = 0; j < 4; j++) {
                wmma::load_matrix_sync(bh[j],
                    sBh + (wn * 64 + j * 16) * LDS_ + kk, LDS_);
                wmma::load_matrix_sync(bl[j],
                    sBl + (wn * 64 + j * 16) * LDS_ + kk, LDS_);
            }
            #pragma unroll
            for (int i = 0; i < 4; i++) {
                wmma::fragment<wmma::matrix_a, 16, 16, 16, __nv_bfloat16,
                               wmma::row_major> ah, al;
                wmma::load_matrix_sync(ah,
                    sAh + (wm * 64 + i * 16) * LDS_ + kk, LDS_);
                wmma::load_matrix_sync(al,
                    sAl + (wm * 64 + i * 16) * LDS_ + kk, LDS_);
                #pragma unroll
                for (int j = 0; j < 4; j++) {
                    wmma::mma_sync(acc[i][j], ah, bh[j], acc[i][j]);
                    wmma::mma_sync(acc[i][j], ah, bl[j], acc[i][j]);
                    wmma::mma_sync(acc[i][j], al, bh[j], acc[i][j]);
                }
            }
        }
        s = (s == NSTAGE - 1) ? 0 : s + 1;
        sl = (sl == NSTAGE - 1) ? 0 : sl + 1;
    }

    __syncthreads();
    float* sf = (float*)smem;
    #pragma unroll
    for (int i = 0; i < 4; i++)
        #pragma unroll
        for (int j = 0; j < 4; j++)
            wmma::store_matrix_sync(
                sf + (wm * 64 + i * 16) * EPI_LD + wn * 64 + j * 16,
                acc[i][j], EPI_LD, wmma::mem_row_major);
    __syncthreads();

    #pragma unroll 4
    for (int it = 0; it < 32; it++) {
        const int idx = tid + it * 256;
        const int rr = idx >> 6;
        const int c4 = (idx & 63) * 4;
        float4 v = *(const float4*)&sf[rr * EPI_LD + c4];
        const int m = mBase + rr;
        const int n = nBase + c4;
        if (EPI == 1 || EPI == 2) {
            const float4 bi = *(const float4*)(bias + n);
            v.x += bi.x; v.y += bi.y; v.z += bi.z; v.w += bi.w;
        }
        if (EPI == 2) {
            v.x = gelu_tanh(v.x); v.y = gelu_tanh(v.y);
            v.z = gelu_tanh(v.z); v.w = gelu_tanh(v.w);
            split_store4(Chi, Clo, (size_t)m * N + n, v.x, v.y, v.z, v.w);
        } else if (EPI == 3) {
            split_store4(Chi, Clo, (size_t)m * N + n, v.x, v.y, v.z, v.w);
        } else {
            if (EPI == 1) {
                const float4 rv = *(const float4*)(res + (size_t)m * N + n);
                v.x += rv.x; v.y += rv.y; v.z += rv.z; v.w += rv.w;
            }
            *(float4*)(C + (size_t)m * N + n) = v;
        }
    }
}

// ---------------------------------------------------------------------------
// WMMA flash attention v3: Q=64, KV=64, 128 threads.
// O lives in accumulator registers across all KV iterations (per-row rescale
// via runtime-discovered fragment row mapping). 2 barriers per iteration.
// K single-buffered, V double-buffered; prefetch overlaps softmax.
// ---------------------------------------------------------------------------
#define FQ_LD 72                         // bf16 ld, 144B rows
#define FS_LD 68                         // fp32 ld, 272B rows
#define OFF_QH 0
#define OFF_QL 9216
#define OFF_KH 18432
#define OFF_KL 27648
#define OFF_VH0 36864
#define OFF_VL0 46080
#define OFF_VH1 55296
#define OFF_VL1 64512
#define OFF_PH 73728
#define OFF_PL 82944
#define OFF_S  92160
#define OFF_M  109568
#define OFF_L  109824
#define OFF_C  110080
#define FAW_SMEM 110336

__global__ __launch_bounds__(128) void flash_attn_w(
    const __nv_bfloat16* __restrict__ qkvh,
    const __nv_bfloat16* __restrict__ qkvl,
    __nv_bfloat16* __restrict__ ohi, __nv_bfloat16* __restrict__ olo)
{
    extern __shared__ char sm8[];
    __nv_bfloat16* sQh = (__nv_bfloat16*)(sm8 + OFF_QH);
    __nv_bfloat16* sQl = (__nv_bfloat16*)(sm8 + OFF_QL);
    __nv_bfloat16* sKh = (__nv_bfloat16*)(sm8 + OFF_KH);
    __nv_bfloat16* sKl = (__nv_bfloat16*)(sm8 + OFF_KL);
    __nv_bfloat16* sVh[2] = { (__nv_bfloat16*)(sm8 + OFF_VH0),
                              (__nv_bfloat16*)(sm8 + OFF_VH1) };
    __nv_bfloat16* sVl[2] = { (__nv_bfloat16*)(sm8 + OFF_VL0),
                              (__nv_bfloat16*)(sm8 + OFF_VL1) };
    __nv_bfloat16* sPh = (__nv_bfloat16*)(sm8 + OFF_PH);
    __nv_bfloat16* sPl = (__nv_bfloat16*)(sm8 + OFF_PL);
    float* sS    = (float*)(sm8 + OFF_S);
    float* mrun  = (float*)(sm8 + OFF_M);
    float* lrun  = (float*)(sm8 + OFF_L);
    float* corrA = (float*)(sm8 + OFF_C);

    const int b = blockIdx.z, h = blockIdx.y;
    const int qb = blockIdx.x * 64;
    const int tid = threadIdx.x;
    const int w = tid >> 5;
    const int wm2 = w >> 1, wn2 = w & 1;
    const uint32_t sbase = smem_to_u32(sm8);

    auto load_k = [&](int kb) {
        const size_t koff = (size_t)(b * L_ + kb) * (3 * D_) + D_ + h * HD_;
        #pragma unroll
        for (int it = 0; it < 4; it++) {
            const int i = it * 128 + tid;
            const int rr = i >> 3, seg = i & 7;
            const uint32_t so = (uint32_t)(rr * FQ_LD + seg * 8) * 2;
            const size_t g = koff + (size_t)rr * (3 * D_) + seg * 8;
            cp16(sbase + OFF_KH + so, qkvh + g);
            cp16(sbase + OFF_KL + so, qkvl + g);
        }
    };
    auto load_v = [&](int kb, int buf) {
        const size_t voff = (size_t)(b * L_ + kb) * (3 * D_) + 2 * D_ + h * HD_;
        const uint32_t dh = buf ? OFF_VH1 : OFF_VH0;
        const uint32_t dl = buf ? OFF_VL1 : OFF_VL0;
        #pragma unroll
        for (int it = 0; it < 4; it++) {
            const int i = it * 128 + tid;
            const int rr = i >> 3, seg = i & 7;
            const uint32_t so = (uint32_t)(rr * FQ_LD + seg * 8) * 2;
            const size_t g = voff + (size_t)rr * (3 * D_) + seg * 8;
            cp16(sbase + dh + so, qkvh + g);
            cp16(sbase + dl + so, qkvl + g);
        }
    };

    // async-load Q hi/lo + K(0) + V(0 -> buf0)
    {
        const size_t qoff = (size_t)(b * L_ + qb) * (3 * D_) + h * HD_;
        #pragma unroll
        for (int it = 0; it < 4; it++) {
            const int i = it * 128 + tid;
            const int rr = i >> 3, seg = i & 7;
            const uint32_t so = (uint32_t)(rr * FQ_LD + seg * 8) * 2;
            const size_t g = qoff + (size_t)rr * (3 * D_) + seg * 8;
            cp16(sbase + OFF_QH + so, qkvh + g);
            cp16(sbase + OFF_QL + so, qkvl + g);
        }
    }
    load_k(0);
    load_v(0, 0);
    CP_COMMIT();
    if (tid < 64) { mrun[tid] = -INFINITY; lrun[tid] = 0.0f; }
    cp_wait_group<0>();
    __syncthreads();

    // --- runtime discovery of accumulator fragment row mapping ---
    wmma::fragment<wmma::accumulator, 16, 16, 16, float> mapf;
    int rowof[mapf.num_elements];
    {
        for (int idx = tid; idx < 256; idx += 128)
            sS[(idx >> 4) * FS_LD + (idx & 15)] = (float)(idx >> 4);
        __syncthreads();
        wmma::load_matrix_sync(mapf, sS, FS_LD, wmma::mem_row_major);
        #pragma unroll
        for (int t = 0; t < mapf.num_elements; t++)
            rowof[t] = (int)mapf.x[t];
        __syncthreads();
    }

    // persistent O accumulators: warp tile rows wm2*32 + i*16, cols wn2*32 + j*16
    wmma::fragment<wmma::accumulator, 16, 16, 16, float> oa[2][2];
    #pragma unroll
    for (int i = 0; i < 2; i++)
        #pragma unroll
        for (int j = 0; j < 2; j++) wmma::fill_fragment(oa[i][j], 0.0f);

    const int r = tid >> 1;          // softmax row 0..63
    const int hf = tid & 1;          // column half

    for (int kb = 0; kb < L_; kb += 64) {
        const int buf = (kb >> 6) & 1;
        const bool more = (kb + 64 < L_);

        // ---- S = Q K^T (bf16x3) ----
        {
            wmma::fragment<wmma::accumulator, 16, 16, 16, float> sa[2][2];
            #pragma unroll
            for (int i = 0; i < 2; i++)
                #pragma unroll
                for (int j = 0; j < 2; j++) wmma::fill_fragment(sa[i][j], 0.0f);
            #pragma unroll
            for (int d = 0; d < HD_; d += 16) {
                wmma::fragment<wmma::matrix_b, 16, 16, 16, __nv_bfloat16,
                               wmma::col_major> bh[2], bl[2];
                #pragma unroll
                for (int j = 0; j < 2; j++) {
                    wmma::load_matrix_sync(bh[j],
                        sKh + (wn2 * 32 + j * 16) * FQ_LD + d, FQ_LD);
                    wmma::load_matrix_sync(bl[j],
                        sKl + (wn2 * 32 + j * 16) * FQ_LD + d, FQ_LD);
                }
                #pragma unroll
                for (int i = 0; i < 2; i++) {
                    wmma::fragment<wmma::matrix_a, 16, 16, 16, __nv_bfloat16,
                                   wmma::row_major> ah, al;
                    wmma::load_matrix_sync(ah,
                        sQh + (wm2 * 32 + i * 16) * FQ_LD + d, FQ_LD);
                    wmma::load_matrix_sync(al,
                        sQl + (wm2 * 32 + i * 16) * FQ_LD + d, FQ_LD);
                    #pragma unroll
                    for (int j = 0; j < 2; j++) {
                        wmma::mma_sync(sa[i][j], ah, bh[j], sa[i][j]);
                        wmma::mma_sync(sa[i][j], ah, bl[j], sa[i][j]);
                        wmma::mma_sync(sa[i][j], al, bh[j], sa[i][j]);
                    }
                }
            }
            #pragma unroll
            for (int i = 0; i < 2; i++)
                #pragma unroll
                for (int j = 0; j < 2; j++)
                    wmma::store_matrix_sync(
                        sS + (wm2 * 32 + i * 16) * FS_LD + wn2 * 32 + j * 16,
                        sa[i][j], FS_LD, wmma::mem_row_major);
        }
        __syncthreads();                       // sync1: S visible, K/V(buf) dead-ok

        // prefetch next K (K dead) and next V (other buffer)
        if (more) {
            load_k(kb + 64);
            load_v(kb + 64, buf ^ 1);
            CP_COMMIT();
        }

        // ---- online softmax (2 threads/row, 32 cols each) ----
        {
            float sv[32];
            float tmax = -INFINITY;
            #pragma unroll
            for (int g = 0; g < 8; g++) {
                const float4 f = *(const float4*)&sS[r * FS_LD + hf * 32 + g * 4];
                sv[g * 4 + 0] = f.x * 0.125f; sv[g * 4 + 1] = f.y * 0.125f;
                sv[g * 4 + 2] = f.z * 0.125f; sv[g * 4 + 3] = f.w * 0.125f;
                tmax = fmaxf(tmax, fmaxf(fmaxf(sv[g*4], sv[g*4+1]),
                                         fmaxf(sv[g*4+2], sv[g*4+3])));
            }
            tmax = fmaxf(tmax, __shfl_xor_sync(0xffffffffu, tmax, 1));
            const float mold = mrun[r];
            const float mnew = fmaxf(mold, tmax);
            const float corr = __expf(mold - mnew);
            float rsum = 0.f;
            #pragma unroll
            for (int g = 0; g < 8; g++) {
                const float p0 = __expf(sv[g*4+0] - mnew);
                const float p1 = __expf(sv[g*4+1] - mnew);
                const float p2 = __expf(sv[g*4+2] - mnew);
                const float p3 = __expf(sv[g*4+3] - mnew);
                rsum += (p0 + p1) + (p2 + p3);
                split_store4(sPh, sPl, (size_t)r * FQ_LD + hf * 32 + g * 4,
                             p0, p1, p2, p3);
            }
            rsum += __shfl_xor_sync(0xffffffffu, rsum, 1);
            if (hf == 0) {
                lrun[r] = lrun[r] * corr + rsum;
                mrun[r] = mnew;
                corrA[r] = corr;
            }
        }
        if (more) cp_wait_group<0>();
        __syncthreads();                       // sync2: P/corr visible, K/V(next) visible

        // ---- rescale O fragments by corr, then accumulate P V (bf16x3) ----
        #pragma unroll
        for (int i = 0; i < 2; i++) {
            #pragma unroll
            for (int j = 0; j < 2; j++) {
                #pragma unroll
                for (int t = 0; t < mapf.num_elements; t++)
                    oa[i][j].x[t] *= corrA[wm2 * 32 + i * 16 + rowof[t]];
            }
        }
        #pragma unroll
        for (int kk = 0; kk < 64; kk += 16) {
            wmma::fragment<wmma::matrix_b, 16, 16, 16, __nv_bfloat16,
                           wmma::row_major> bh[2], bl[2];
            #pragma unroll
            for (int j = 0; j < 2; j++) {
                wmma::load_matrix_sync(bh[j],
                    sVh[buf] + kk * FQ_LD + wn2 * 32 + j * 16, FQ_LD);
                wmma::load_matrix_sync(bl[j],
                    sVl[buf] + kk * FQ_LD + wn2 * 32 + j * 16, FQ_LD);
            }
            #pragma unroll
            for (int i = 0; i < 2; i++) {
                wmma::fragment<wmma::matrix_a, 16, 16, 16, __nv_bfloat16,
                               wmma::row_major> ah, al;
                wmma::load_matrix_sync(ah,
                    sPh + (wm2 * 32 + i * 16) * FQ_LD + kk, FQ_LD);
                wmma::load_matrix_sync(al,
                    sPl + (wm2 * 32 + i * 16) * FQ_LD + kk, FQ_LD);
                #pragma unroll
                for (int j = 0; j < 2; j++) {
                    wmma::mma_sync(oa[i][j], ah, bh[j], oa[i][j]);
                    wmma::mma_sync(oa[i][j], ah, bl[j], oa[i][j]);
                    wmma::mma_sync(oa[i][j], al, bh[j], oa[i][j]);
                }
            }
        }
        // no barrier here: next S-MMA writes sS (consumed; all warps passed
        // sync2), and next softmax's P writes wait on next sync1.
    }

    // ---- epilogue: O fragments -> sS -> normalize + split-store ----
    #pragma unroll
    for (int i = 0; i < 2; i++)
        #pragma unroll
        for (int j = 0; j < 2; j++)
            wmma::store_matrix_sync(
                sS + (wm2 * 32 + i * 16) * FS_LD + wn2 * 32 + j * 16,
                oa[i][j], FS_LD, wmma::mem_row_major);
    __syncthreads();
    {
        const float inv = 1.0f / lrun[r];
        #pragma unroll
        for (int g = 0; g < 8; g++) {
            const float4 ov = *(const float4*)&sS[r * FS_LD + hf * 32 + g * 4];
            split_store4(ohi, olo,
                (size_t)(b * L_ + qb + r) * D_ + h * HD_ + hf * 32 + g * 4,
                ov.x * inv, ov.y * inv, ov.z * inv, ov.w * inv);
        }
    }
}

// ---------------------------------------------------------------------------
// Launch
// ---------------------------------------------------------------------------
extern "C" void kernel_launch(void* const* d_in, const int* in_sizes, int n_in,
                              void* d_out, int out_size)
{
    const float* x      = (const float*)d_in[0];
    const float* ln1_s  = (const float*)d_in[1];
    const float* ln1_b  = (const float*)d_in[2];
    const float* w_qkv  = (const float*)d_in[3];
    const float* w_proj = (const float*)d_in[4];
    const float* b_proj = (const float*)d_in[5];
    const float* ln2_s  = (const float*)d_in[6];
    const float* ln2_b  = (const float*)d_in[7];
    const float* w_mlp1 = (const float*)d_in[8];
    const float* b_mlp1 = (const float*)d_in[9];
    const float* w_mlp2 = (const float*)d_in[10];
    const float* b_mlp2 = (const float*)d_in[11];
    float* out = (float*)d_out;

    __nv_bfloat16 *hhi, *hlo, *qkvh, *qkvl, *athi, *atlo, *midhi, *midlo;
    __nv_bfloat16 *wqh, *wql, *wph, *wpl, *w1h, *w1l, *w2h, *w2l;
    float *x1;
    cudaGetSymbolAddress((void**)&hhi, g_h_hi);
    cudaGetSymbolAddress((void**)&hlo, g_h_lo);
    cudaGetSymbolAddress((void**)&qkvh, g_qkv_hi);
    cudaGetSymbolAddress((void**)&qkvl, g_qkv_lo);
    cudaGetSymbolAddress((void**)&athi, g_at_hi);
    cudaGetSymbolAddress((void**)&atlo, g_at_lo);
    cudaGetSymbolAddress((void**)&x1, g_x1);
    cudaGetSymbolAddress((void**)&midhi, g_mid_hi);
    cudaGetSymbolAddress((void**)&midlo, g_mid_lo);
    cudaGetSymbolAddress((void**)&wqh, g_wqkv_hi);
    cudaGetSymbolAddress((void**)&wql, g_wqkv_lo);
    cudaGetSymbolAddress((void**)&wph, g_wpr_hi);
    cudaGetSymbolAddress((void**)&wpl, g_wpr_lo);
    cudaGetSymbolAddress((void**)&w1h, g_wm1_hi);
    cudaGetSymbolAddress((void**)&w1l, g_wm1_lo);
    cudaGetSymbolAddress((void**)&w2h, g_wm2_hi);
    cudaGetSymbolAddress((void**)&w2l, g_wm2_lo);

    static bool attr_set = false;
    if (!attr_set) {
        cudaFuncSetAttribute(flash_attn_w,
            cudaFuncAttributeMaxDynamicSharedMemorySize, FAW_SMEM);
        cudaFuncSetAttribute(wm_gemm<1>,
            cudaFuncAttributeMaxDynamicSharedMemorySize, GEMM_SMEM);
        cudaFuncSetAttribute(wm_gemm<2>,
            cudaFuncAttributeMaxDynamicSharedMemorySize, GEMM_SMEM);
        cudaFuncSetAttribute(wm_gemm<3>,
            cudaFuncAttributeMaxDynamicSharedMemorySize, GEMM_SMEM);
        attr_set = true;
    }

    const dim3 tb(32, 8);
    wsplit_t<<<dim3(3 * D_ / 32, D_ / 32), tb>>>(w_qkv, wqh, wql, D_, 3 * D_);
    wsplit_t<<<dim3(D_ / 32, D_ / 32), tb>>>(w_proj, wph, wpl, D_, D_);
    wsplit_t<<<dim3(F_ / 32, D_ / 32), tb>>>(w_mlp1, w1h, w1l, D_, F_);
    wsplit_t<<<dim3(D_ / 32, F_ / 32), tb>>>(w_mlp2, w2h, w2l, F_, D_);

    // 1) pre-norm 1 -> bf16 hi/lo
    layernorm_k<<<M_, 256>>>(x, ln1_s, ln1_b, hhi, hlo);
    // 2) qkv projection -> bf16 hi/lo directly
    wm_gemm<3><<<dim3(3 * D_ / BN, M_ / BM), 256, GEMM_SMEM>>>(
        hhi, hlo, wqh, wql, nullptr, nullptr, nullptr, qkvh, qkvl,
        M_, 3 * D_, D_);
    // 3) attention (wmma bf16x3, register-resident O) -> bf16 hi/lo
    flash_attn_w<<<dim3(L_ / 64, H_, B_), 128, FAW_SMEM>>>(
        qkvh, qkvl, athi, atlo);
    // 4) out proj + bias + residual -> fp32 x1
    wm_gemm<1><<<dim3(D_ / BN, M_ / BM), 256, GEMM_SMEM>>>(
        athi, atlo, wph, wpl, b_proj, x, x1, nullptr, nullptr,
        M_, D_, D_);
    // 5) pre-norm 2 -> bf16 hi/lo
    layernorm_k<<<M_, 256>>>(x1, ln2_s, ln2_b, hhi, hlo);
    // 6) MLP up + bias + gelu -> bf16 hi/lo
    wm_gemm<2><<<dim3(F_ / BN, M_ / BM), 256, GEMM_SMEM>>>(
        hhi, hlo, w1h, w1l, b_mlp1, nullptr, nullptr, midhi, midlo,
        M_, F_, D_);
    // 7) MLP down + bias + residual -> final out
    wm_gemm<1><<<dim3(D_ / BN, M_ / BM), 256, GEMM_SMEM>>>(
        midhi, midlo, w2h, w2l, b_mlp2, x1, out, nullptr, nullptr,
        M_, D_, F_);
}

// round 15
// speedup vs baseline: 1.1416x; 1.0166x over previous
#include <cuda_runtime.h>
#include <cuda_bf16.h>
#include <mma.h>
#include <math.h>
#include <stdint.h>

using namespace nvcuda;

// Problem constants
#define B_ 2
#define L_ 2048
#define D_ 1024
#define F_ 4096
#define H_ 16
#define HD_ 64
#define M_ (B_ * L_)
#define LN_EPS 1e-6f

// ---------------------------------------------------------------------------
// Scratch (static device globals; no allocation anywhere)
// ---------------------------------------------------------------------------
__device__ __nv_bfloat16 g_h_hi[M_ * D_];
__device__ __nv_bfloat16 g_h_lo[M_ * D_];
__device__ __nv_bfloat16 g_qkv_hi[M_ * 3 * D_];
__device__ __nv_bfloat16 g_qkv_lo[M_ * 3 * D_];
__device__ __nv_bfloat16 g_at_hi[M_ * D_];
__device__ __nv_bfloat16 g_at_lo[M_ * D_];
__device__ float         g_x1[M_ * D_];
__device__ __nv_bfloat16 g_mid_hi[M_ * F_];
__device__ __nv_bfloat16 g_mid_lo[M_ * F_];
// weights transposed to [N][K], split hi/lo
__device__ __nv_bfloat16 g_wqkv_hi[3 * D_ * D_];
__device__ __nv_bfloat16 g_wqkv_lo[3 * D_ * D_];
__device__ __nv_bfloat16 g_wpr_hi[D_ * D_];
__device__ __nv_bfloat16 g_wpr_lo[D_ * D_];
__device__ __nv_bfloat16 g_wm1_hi[F_ * D_];
__device__ __nv_bfloat16 g_wm1_lo[F_ * D_];
__device__ __nv_bfloat16 g_wm2_hi[D_ * F_];
__device__ __nv_bfloat16 g_wm2_lo[D_ * F_];

// ---------------------------------------------------------------------------
// helpers
// ---------------------------------------------------------------------------
__device__ __forceinline__ uint32_t smem_to_u32(const void* p) {
    uint32_t a;
    asm("{ .reg .u64 t; cvta.to.shared.u64 t, %1; cvt.u32.u64 %0, t; }"
        : "=r"(a) : "l"(p));
    return a;
}

__device__ __forceinline__ void cp16(uint32_t daddr, const void* g) {
    asm volatile("cp.async.cg.shared.global [%0], [%1], 16;"
                 :: "r"(daddr), "l"(g));
}
#define CP_COMMIT() asm volatile("cp.async.commit_group;" ::: "memory")
template <int N>
__device__ __forceinline__ void cp_wait_group() {
    asm volatile("cp.async.wait_group %0;" :: "n"(N) : "memory");
}

__device__ __forceinline__ uint32_t bf2u(__nv_bfloat16 a, __nv_bfloat16 b) {
    return (uint32_t)__bfloat16_as_ushort(a) |
           ((uint32_t)__bfloat16_as_ushort(b) << 16);
}

__device__ __forceinline__ void split_store4(
    __nv_bfloat16* __restrict__ hi, __nv_bfloat16* __restrict__ lo,
    size_t off, float a, float b, float c, float d)
{
    __nv_bfloat16 h0 = __float2bfloat16(a), h1 = __float2bfloat16(b);
    __nv_bfloat16 h2 = __float2bfloat16(c), h3 = __float2bfloat16(d);
    __nv_bfloat16 l0 = __float2bfloat16(a - __bfloat162float(h0));
    __nv_bfloat16 l1 = __float2bfloat16(b - __bfloat162float(h1));
    __nv_bfloat16 l2 = __float2bfloat16(c - __bfloat162float(h2));
    __nv_bfloat16 l3 = __float2bfloat16(d - __bfloat162float(h3));
    *(uint2*)(hi + off) = make_uint2(bf2u(h0, h1), bf2u(h2, h3));
    *(uint2*)(lo + off) = make_uint2(bf2u(l0, l1), bf2u(l2, l3));
}

__device__ __forceinline__ float gelu_tanh(float v) {
    const float c = 0.7978845608028654f;
    float u = c * (v + 0.044715f * v * v * v);
    return 0.5f * v * (1.0f + tanhf(u));
}

// ---------------------------------------------------------------------------
// Weight transpose + split: W[K][N] -> hi/lo[N][K] bf16
// ---------------------------------------------------------------------------
__global__ __launch_bounds__(256) void wsplit_t(
    const float* __restrict__ W, __nv_bfloat16* __restrict__ hi,
    __nv_bfloat16* __restrict__ lo, int K, int N)
{
    __shared__ float t[32][33];
    const int n0 = blockIdx.x * 32, k0 = blockIdx.y * 32;
    const int tx = threadIdx.x, ty = threadIdx.y;
    #pragma unroll
    for (int i = ty; i < 32; i += 8)
        t[i][tx] = W[(size_t)(k0 + i) * N + n0 + tx];
    __syncthreads();
    #pragma unroll
    for (int i = ty; i < 32; i += 8) {
        const float v = t[tx][i];
        const __nv_bfloat16 h = __float2bfloat16(v);
        const __nv_bfloat16 l = __float2bfloat16(v - __bfloat162float(h));
        const size_t o = (size_t)(n0 + i) * K + k0 + tx;
        hi[o] = h; lo[o] = l;
    }
}

// ---------------------------------------------------------------------------
// LayerNorm -> bf16 hi/lo
// ---------------------------------------------------------------------------
__global__ __launch_bounds__(256) void layernorm_k(
    const float* __restrict__ x, const float* __restrict__ gamma,
    const float* __restrict__ beta,
    __nv_bfloat16* __restrict__ ohi, __nv_bfloat16* __restrict__ olo)
{
    const int row = blockIdx.x;
    const int t = threadIdx.x;
    const float4 v = *(const float4*)(x + (size_t)row * D_ + t * 4);

    float s = v.x + v.y + v.z + v.w;
    float q = v.x * v.x + v.y * v.y + v.z * v.z + v.w * v.w;
    #pragma unroll
    for (int off = 16; off > 0; off >>= 1) {
        s += __shfl_down_sync(0xffffffffu, s, off);
        q += __shfl_down_sync(0xffffffffu, q, off);
    }
    __shared__ float ss[8], qq[8];
    const int wid = t >> 5, lane = t & 31;
    if (lane == 0) { ss[wid] = s; qq[wid] = q; }
    __syncthreads();
    if (t == 0) {
        float S = 0.f, Q = 0.f;
        #pragma unroll
        for (int i = 0; i < 8; i++) { S += ss[i]; Q += qq[i]; }
        ss[0] = S; qq[0] = Q;
    }
    __syncthreads();
    const float mu = ss[0] * (1.0f / D_);
    const float var = qq[0] * (1.0f / D_) - mu * mu;
    const float rstd = rsqrtf(var + LN_EPS);

    const float4 g4 = *(const float4*)(gamma + t * 4);
    const float4 b4 = *(const float4*)(beta + t * 4);
    const float ox = (v.x - mu) * rstd * g4.x + b4.x;
    const float oy = (v.y - mu) * rstd * g4.y + b4.y;
    const float oz = (v.z - mu) * rstd * g4.z + b4.z;
    const float ow = (v.w - mu) * rstd * g4.w + b4.w;
    split_store4(ohi, olo, (size_t)row * D_ + t * 4, ox, oy, oz, ow);
}

// ---------------------------------------------------------------------------
// WMMA GEMM: bf16x3, 128x256 tile, 3-stage cp.async (unchanged, proven).
// EPI: 0 = fp32 out, 1 = +bias +residual -> fp32,
//      2 = +bias +gelu -> bf16 hi/lo, 3 = split -> bf16 hi/lo (no bias)
// ---------------------------------------------------------------------------
#define BM 128
#define BN 256
#define BK 32
#define NSTAGE 3
#define LDS_ 40
#define A_EL (128 * LDS_)
#define B_EL (256 * LDS_)
#define STAGE_EL (2 * A_EL + 2 * B_EL)
#define EPI_LD 260
#define GEMM_SMEM (NSTAGE * STAGE_EL * 2)

template <int EPI>
__global__ __launch_bounds__(256, 1) void wm_gemm(
    const __nv_bfloat16* __restrict__ Ahi, const __nv_bfloat16* __restrict__ Alo,
    const __nv_bfloat16* __restrict__ Bhi, const __nv_bfloat16* __restrict__ Blo,
    const float* __restrict__ bias, const float* __restrict__ res,
    float* __restrict__ C, __nv_bfloat16* __restrict__ Chi,
    __nv_bfloat16* __restrict__ Clo, int M, int N, int K)
{
    extern __shared__ char smem[];
    __nv_bfloat16* sb = (__nv_bfloat16*)smem;
    const uint32_t sbase = smem_to_u32(smem);
    const int tid = threadIdx.x;
    const int w = tid >> 5;
    const int wm = w >> 2;
    const int wn = w & 3;
    const int mBase = blockIdx.y * BM;
    const int nBase = blockIdx.x * BN;

    const __nv_bfloat16* gsrc[4] = {
        Ahi + (size_t)mBase * K,
        Alo + (size_t)mBase * K,
        Bhi + (size_t)nBase * K,
        Blo + (size_t)nBase * K };
    const int unit_of_it[12]  = {0,0, 1,1, 2,2,2,2, 3,3,3,3};
    const int rbase_of_it[12] = {0,0, 128,128, 256,256,256,256, 512,512,512,512};
    const int soff_of_unit[4] = {0, A_EL, 2 * A_EL, 2 * A_EL + B_EL};

    wmma::fragment<wmma::accumulator, 16, 16, 16, float> acc[4][4];
    #pragma unroll
    for (int i = 0; i < 4; i++)
        #pragma unroll
        for (int j = 0; j < 4; j++)
            wmma::fill_fragment(acc[i][j], 0.0f);

    const int nchunks = K / BK;

    auto load_stage = [&](int stg, int k0) {
        const uint32_t so = sbase + (uint32_t)stg * STAGE_EL * 2;
        #pragma unroll
        for (int it = 0; it < 12; it++) {
            const int idx = it * 256 + tid;
            const int r = idx >> 2;
            const int seg = idx & 3;
            const int u = unit_of_it[it];
            const int lr = r - rbase_of_it[it];
            cp16(so + (uint32_t)(soff_of_unit[u] + lr * LDS_ + seg * 8) * 2,
                 gsrc[u] + (size_t)lr * K + k0 + seg * 8);
        }
    };

    load_stage(0, 0);
    CP_COMMIT();
    load_stage(1, BK);
    CP_COMMIT();

    int s = 0, sl = 2;
    for (int c = 0; c < nchunks; c++) {
        cp_wait_group<1>();
        __syncthreads();
        if (c + 2 < nchunks) {
            load_stage(sl, (c + 2) * BK);
            CP_COMMIT();
        }
        const __nv_bfloat16* st = sb + s * STAGE_EL;
        const __nv_bfloat16* sAh = st;
        const __nv_bfloat16* sAl = st + A_EL;
        const __nv_bfloat16* sBh = st + 2 * A_EL;
        const __nv_bfloat16* sBl = st + 2 * A_EL + B_EL;

        #pragma unroll
        for (int kk = 0; kk < BK; kk += 16) {
            wmma::fragment<wmma::matrix_b, 16, 16, 16, __nv_bfloat16,
                           wmma::col_major> bh[4], bl[4];
            #pragma unroll
            for (int j = 0; j < 4; j++) {
                wmma::load_matrix_sync(bh[j],
                    sBh + (wn * 64 + j * 16) * LDS_ + kk, LDS_);
                wmma::load_matrix_sync(bl[j],
                    sBl + (wn * 64 + j * 16) * LDS_ + kk, LDS_);
            }
            #pragma unroll
            for (int i = 0; i < 4; i++) {
                wmma::fragment<wmma::matrix_a, 16, 16, 16, __nv_bfloat16,
                               wmma::row_major> ah, al;
                wmma::load_matrix_sync(ah,
                    sAh + (wm * 64 + i * 16) * LDS_ + kk, LDS_);
                wmma::load_matrix_sync(al,
                    sAl + (wm * 64 + i * 16) * LDS_ + kk, LDS_);
                #pragma unroll
                for (int j = 0; j < 4; j++) {
                    wmma::mma_sync(acc[i][j], ah, bh[j], acc[i][j]);
                    wmma::mma_sync(acc[i][j], ah, bl[j], acc[i][j]);
                    wmma::mma_sync(acc[i][j], al, bh[j], acc[i][j]);
                }
            }
        }
        s = (s == NSTAGE - 1) ? 0 : s + 1;
        sl = (sl == NSTAGE - 1) ? 0 : sl + 1;
    }

    __syncthreads();
    float* sf = (float*)smem;
    #pragma unroll
    for (int i = 0; i < 4; i++)
        #pragma unroll
        for (int j = 0; j < 4; j++)
            wmma::store_matrix_sync(
                sf + (wm * 64 + i * 16) * EPI_LD + wn * 64 + j * 16,
                acc[i][j], EPI_LD, wmma::mem_row_major);
    __syncthreads();

    #pragma unroll 4
    for (int it = 0; it < 32; it++) {
        const int idx = tid + it * 256;
        const int rr = idx >> 6;
        const int c4 = (idx & 63) * 4;
        float4 v = *(const float4*)&sf[rr * EPI_LD + c4];
        const int m = mBase + rr;
        const int n = nBase + c4;
        if (EPI == 1 || EPI == 2) {
            const float4 bi = *(const float4*)(bias + n);
            v.x += bi.x; v.y += bi.y; v.z += bi.z; v.w += bi.w;
        }
        if (EPI == 2) {
            v.x = gelu_tanh(v.x); v.y = gelu_tanh(v.y);
            v.z = gelu_tanh(v.z); v.w = gelu_tanh(v.w);
            split_store4(Chi, Clo, (size_t)m * N + n, v.x, v.y, v.z, v.w);
        } else if (EPI == 3) {
            split_store4(Chi, Clo, (size_t)m * N + n, v.x, v.y, v.z, v.w);
        } else {
            if (EPI == 1) {
                const float4 rv = *(const float4*)(res + (size_t)m * N + n);
                v.x += rv.x; v.y += rv.y; v.z += rv.z; v.w += rv.w;
            }
            *(float4*)(C + (size_t)m * N + n) = v;
        }
    }
}

// ---------------------------------------------------------------------------
// WMMA flash attention v3 (unchanged from R13): Q=64, KV=64, 128 threads,
// register-resident O with runtime fragment row mapping, 2 barriers/iter,
// K single-buffered + V double-buffered prefetch.
// ---------------------------------------------------------------------------
#define FQ_LD 72                         // bf16 ld, 144B rows
#define FS_LD 68                         // fp32 ld, 272B rows
#define OFF_QH 0
#define OFF_QL 9216
#define OFF_KH 18432
#define OFF_KL 27648
#define OFF_VH0 36864
#define OFF_VL0 46080
#define OFF_VH1 55296
#define OFF_VL1 64512
#define OFF_PH 73728
#define OFF_PL 82944
#define OFF_S  92160
#define OFF_M  109568
#define OFF_L  109824
#define OFF_C  110080
#define FAW_SMEM 110336

__global__ __launch_bounds__(128) void flash_attn_w(
    const __nv_bfloat16* __restrict__ qkvh,
    const __nv_bfloat16* __restrict__ qkvl,
    __nv_bfloat16* __restrict__ ohi, __nv_bfloat16* __restrict__ olo)
{
    extern __shared__ char sm8[];
    __nv_bfloat16* sQh = (__nv_bfloat16*)(sm8 + OFF_QH);
    __nv_bfloat16* sQl = (__nv_bfloat16*)(sm8 + OFF_QL);
    __nv_bfloat16* sKh = (__nv_bfloat16*)(sm8 + OFF_KH);
    __nv_bfloat16* sKl = (__nv_bfloat16*)(sm8 + OFF_KL);
    __nv_bfloat16* sVh[2] = { (__nv_bfloat16*)(sm8 + OFF_VH0),
                              (__nv_bfloat16*)(sm8 + OFF_VH1) };
    __nv_bfloat16* sVl[2] = { (__nv_bfloat16*)(sm8 + OFF_VL0),
                              (__nv_bfloat16*)(sm8 + OFF_VL1) };
    __nv_bfloat16* sPh = (__nv_bfloat16*)(sm8 + OFF_PH);
    __nv_bfloat16* sPl = (__nv_bfloat16*)(sm8 + OFF_PL);
    float* sS    = (float*)(sm8 + OFF_S);
    float* mrun  = (float*)(sm8 + OFF_M);
    float* lrun  = (float*)(sm8 + OFF_L);
    float* corrA = (float*)(sm8 + OFF_C);

    const int b = blockIdx.z, h = blockIdx.y;
    const int qb = blockIdx.x * 64;
    const int tid = threadIdx.x;
    const int w = tid >> 5;
    const int wm2 = w >> 1, wn2 = w & 1;
    const uint32_t sbase = smem_to_u32(sm8);

    auto load_k = [&](int kb) {
        const size_t koff = (size_t)(b * L_ + kb) * (3 * D_) + D_ + h * HD_;
        #pragma unroll
        for (int it = 0; it < 4; it++) {
            const int i = it * 128 + tid;
            const int rr = i >> 3, seg = i & 7;
            const uint32_t so = (uint32_t)(rr * FQ_LD + seg * 8) * 2;
            const size_t g = koff + (size_t)rr * (3 * D_) + seg * 8;
            cp16(sbase + OFF_KH + so, qkvh + g);
            cp16(sbase + OFF_KL + so, qkvl + g);
        }
    };
    auto load_v = [&](int kb, int buf) {
        const size_t voff = (size_t)(b * L_ + kb) * (3 * D_) + 2 * D_ + h * HD_;
        const uint32_t dh = buf ? OFF_VH1 : OFF_VH0;
        const uint32_t dl = buf ? OFF_VL1 : OFF_VL0;
        #pragma unroll
        for (int it = 0; it < 4; it++) {
            const int i = it * 128 + tid;
            const int rr = i >> 3, seg = i & 7;
            const uint32_t so = (uint32_t)(rr * FQ_LD + seg * 8) * 2;
            const size_t g = voff + (size_t)rr * (3 * D_) + seg * 8;
            cp16(sbase + dh + so, qkvh + g);
            cp16(sbase + dl + so, qkvl + g);
        }
    };

    // async-load Q hi/lo + K(0) + V(0 -> buf0)
    {
        const size_t qoff = (size_t)(b * L_ + qb) * (3 * D_) + h * HD_;
        #pragma unroll
        for (int it = 0; it < 4; it++) {
            const int i = it * 128 + tid;
            const int rr = i >> 3, seg = i & 7;
            const uint32_t so = (uint32_t)(rr * FQ_LD + seg * 8) * 2;
            const size_t g = qoff + (size_t)rr * (3 * D_) + seg * 8;
            cp16(sbase + OFF_QH + so, qkvh + g);
            cp16(sbase + OFF_QL + so, qkvl + g);
        }
    }
    load_k(0);
    load_v(0, 0);
    CP_COMMIT();
    if (tid < 64) { mrun[tid] = -INFINITY; lrun[tid] = 0.0f; }
    cp_wait_group<0>();
    __syncthreads();

    // --- runtime discovery of accumulator fragment row mapping ---
    wmma::fragment<wmma::accumulator, 16, 16, 16, float> mapf;
    int rowof[mapf.num_elements];
    {
        for (int idx = tid; idx < 256; idx += 128)
            sS[(idx >> 4) * FS_LD + (idx & 15)] = (float)(idx >> 4);
        __syncthreads();
        wmma::load_matrix_sync(mapf, sS, FS_LD, wmma::mem_row_major);
        #pragma unroll
        for (int t = 0; t < mapf.num_elements; t++)
            rowof[t] = (int)mapf.x[t];
        __syncthreads();
    }

    // persistent O accumulators
    wmma::fragment<wmma::accumulator, 16, 16, 16, float> oa[2][2];
    #pragma unroll
    for (int i = 0; i < 2; i++)
        #pragma unroll
        for (int j = 0; j < 2; j++) wmma::fill_fragment(oa[i][j], 0.0f);

    const int r = tid >> 1;
    const int hf = tid & 1;

    for (int kb = 0; kb < L_; kb += 64) {
        const int buf = (kb >> 6) & 1;
        const bool more = (kb + 64 < L_);

        // ---- S = Q K^T (bf16x3) ----
        {
            wmma::fragment<wmma::accumulator, 16, 16, 16, float> sa[2][2];
            #pragma unroll
            for (int i = 0; i < 2; i++)
                #pragma unroll
                for (int j = 0; j < 2; j++) wmma::fill_fragment(sa[i][j], 0.0f);
            #pragma unroll
            for (int d = 0; d < HD_; d += 16) {
                wmma::fragment<wmma::matrix_b, 16, 16, 16, __nv_bfloat16,
                               wmma::col_major> bh[2], bl[2];
                #pragma unroll
                for (int j = 0; j < 2; j++) {
                    wmma::load_matrix_sync(bh[j],
                        sKh + (wn2 * 32 + j * 16) * FQ_LD + d, FQ_LD);
                    wmma::load_matrix_sync(bl[j],
                        sKl + (wn2 * 32 + j * 16) * FQ_LD + d, FQ_LD);
                }
                #pragma unroll
                for (int i = 0; i < 2; i++) {
                    wmma::fragment<wmma::matrix_a, 16, 16, 16, __nv_bfloat16,
                                   wmma::row_major> ah, al;
                    wmma::load_matrix_sync(ah,
                        sQh + (wm2 * 32 + i * 16) * FQ_LD + d, FQ_LD);
                    wmma::load_matrix_sync(al,
                        sQl + (wm2 * 32 + i * 16) * FQ_LD + d, FQ_LD);
                    #pragma unroll
                    for (int j = 0; j < 2; j++) {
                        wmma::mma_sync(sa[i][j], ah, bh[j], sa[i][j]);
                        wmma::mma_sync(sa[i][j], ah, bl[j], sa[i][j]);
                        wmma::mma_sync(sa[i][j], al, bh[j], sa[i][j]);
                    }
                }
            }
            #pragma unroll
            for (int i = 0; i < 2; i++)
                #pragma unroll
                for (int j = 0; j < 2; j++)
                    wmma::store_matrix_sync(
                        sS + (wm2 * 32 + i * 16) * FS_LD + wn2 * 32 + j * 16,
                        sa[i][j], FS_LD, wmma::mem_row_major);
        }
        __syncthreads();                       // sync1

        if (more) {
            load_k(kb + 64);
            load_v(kb + 64, buf ^ 1);
            CP_COMMIT();
        }

        // ---- online softmax ----
        {
            float sv[32];
            float tmax = -INFINITY;
            #pragma unroll
            for (int g = 0; g < 8; g++) {
                const float4 f = *(const float4*)&sS[r * FS_LD + hf * 32 + g * 4];
                sv[g * 4 + 0] = f.x * 0.125f; sv[g * 4 + 1] = f.y * 0.125f;
                sv[g * 4 + 2] = f.z * 0.125f; sv[g * 4 + 3] = f.w * 0.125f;
                tmax = fmaxf(tmax, fmaxf(fmaxf(sv[g*4], sv[g*4+1]),
                                         fmaxf(sv[g*4+2], sv[g*4+3])));
            }
            tmax = fmaxf(tmax, __shfl_xor_sync(0xffffffffu, tmax, 1));
            const float mold = mrun[r];
            const float mnew = fmaxf(mold, tmax);
            const float corr = __expf(mold - mnew);
            float rsum = 0.f;
            #pragma unroll
            for (int g = 0; g < 8; g++) {
                const float p0 = __expf(sv[g*4+0] - mnew);
                const float p1 = __expf(sv[g*4+1] - mnew);
                const float p2 = __expf(sv[g*4+2] - mnew);
                const float p3 = __expf(sv[g*4+3] - mnew);
                rsum += (p0 + p1) + (p2 + p3);
                split_store4(sPh, sPl, (size_t)r * FQ_LD + hf * 32 + g * 4,
                             p0, p1, p2, p3);
            }
            rsum += __shfl_xor_sync(0xffffffffu, rsum, 1);
            if (hf == 0) {
                lrun[r] = lrun[r] * corr + rsum;
                mrun[r] = mnew;
                corrA[r] = corr;
            }
        }
        if (more) cp_wait_group<0>();
        __syncthreads();                       // sync2

        // ---- rescale O fragments, accumulate P V (bf16x3) ----
        #pragma unroll
        for (int i = 0; i < 2; i++) {
            #pragma unroll
            for (int j = 0; j < 2; j++) {
                #pragma unroll
                for (int t = 0; t < mapf.num_elements; t++)
                    oa[i][j].x[t] *= corrA[wm2 * 32 + i * 16 + rowof[t]];
            }
        }
        #pragma unroll
        for (int kk = 0; kk < 64; kk += 16) {
            wmma::fragment<wmma::matrix_b, 16, 16, 16, __nv_bfloat16,
                           wmma::row_major> bh[2], bl[2];
            #pragma unroll
            for (int j = 0; j < 2; j++) {
                wmma::load_matrix_sync(bh[j],
                    sVh[buf] + kk * FQ_LD + wn2 * 32 + j * 16, FQ_LD);
                wmma::load_matrix_sync(bl[j],
                    sVl[buf] + kk * FQ_LD + wn2 * 32 + j * 16, FQ_LD);
            }
            #pragma unroll
            for (int i = 0; i < 2; i++) {
                wmma::fragment<wmma::matrix_a, 16, 16, 16, __nv_bfloat16,
                               wmma::row_major> ah, al;
                wmma::load_matrix_sync(ah,
                    sPh + (wm2 * 32 + i * 16) * FQ_LD + kk, FQ_LD);
                wmma::load_matrix_sync(al,
                    sPl + (wm2 * 32 + i * 16) * FQ_LD + kk, FQ_LD);
                #pragma unroll
                for (int j = 0; j < 2; j++) {
                    wmma::mma_sync(oa[i][j], ah, bh[j], oa[i][j]);
                    wmma::mma_sync(oa[i][j], ah, bl[j], oa[i][j]);
                    wmma::mma_sync(oa[i][j], al, bh[j], oa[i][j]);
                }
            }
        }
    }

    // ---- epilogue ----
    #pragma unroll
    for (int i = 0; i < 2; i++)
        #pragma unroll
        for (int j = 0; j < 2; j++)
            wmma::store_matrix_sync(
                sS + (wm2 * 32 + i * 16) * FS_LD + wn2 * 32 + j * 16,
                oa[i][j], FS_LD, wmma::mem_row_major);
    __syncthreads();
    {
        const float inv = 1.0f / lrun[r];
        #pragma unroll
        for (int g = 0; g < 8; g++) {
            const float4 ov = *(const float4*)&sS[r * FS_LD + hf * 32 + g * 4];
            split_store4(ohi, olo,
                (size_t)(b * L_ + qb + r) * D_ + h * HD_ + hf * 32 + g * 4,
                ov.x * inv, ov.y * inv, ov.z * inv, ov.w * inv);
        }
    }
}

// ---------------------------------------------------------------------------
// Launch — side stream runs the weight splits concurrently with the main
// chain (fork/join via events; capturable graph topology).
// ---------------------------------------------------------------------------
static cudaStream_t g_side = nullptr;
static cudaEvent_t  g_ev_fork = nullptr;
static cudaEvent_t  g_ev_qkvw = nullptr;
static cudaEvent_t  g_ev_allw = nullptr;

extern "C" void kernel_launch(void* const* d_in, const int* in_sizes, int n_in,
                              void* d_out, int out_size)
{
    const float* x      = (const float*)d_in[0];
    const float* ln1_s  = (const float*)d_in[1];
    const float* ln1_b  = (const float*)d_in[2];
    const float* w_qkv  = (const float*)d_in[3];
    const float* w_proj = (const float*)d_in[4];
    const float* b_proj = (const float*)d_in[5];
    const float* ln2_s  = (const float*)d_in[6];
    const float* ln2_b  = (const float*)d_in[7];
    const float* w_mlp1 = (const float*)d_in[8];
    const float* b_mlp1 = (const float*)d_in[9];
    const float* w_mlp2 = (const float*)d_in[10];
    const float* b_mlp2 = (const float*)d_in[11];
    float* out = (float*)d_out;

    __nv_bfloat16 *hhi, *hlo, *qkvh, *qkvl, *athi, *atlo, *midhi, *midlo;
    __nv_bfloat16 *wqh, *wql, *wph, *wpl, *w1h, *w1l, *w2h, *w2l;
    float *x1;
    cudaGetSymbolAddress((void**)&hhi, g_h_hi);
    cudaGetSymbolAddress((void**)&hlo, g_h_lo);
    cudaGetSymbolAddress((void**)&qkvh, g_qkv_hi);
    cudaGetSymbolAddress((void**)&qkvl, g_qkv_lo);
    cudaGetSymbolAddress((void**)&athi, g_at_hi);
    cudaGetSymbolAddress((void**)&atlo, g_at_lo);
    cudaGetSymbolAddress((void**)&x1, g_x1);
    cudaGetSymbolAddress((void**)&midhi, g_mid_hi);
    cudaGetSymbolAddress((void**)&midlo, g_mid_lo);
    cudaGetSymbolAddress((void**)&wqh, g_wqkv_hi);
    cudaGetSymbolAddress((void**)&wql, g_wqkv_lo);
    cudaGetSymbolAddress((void**)&wph, g_wpr_hi);
    cudaGetSymbolAddress((void**)&wpl, g_wpr_lo);
    cudaGetSymbolAddress((void**)&w1h, g_wm1_hi);
    cudaGetSymbolAddress((void**)&w1l, g_wm1_lo);
    cudaGetSymbolAddress((void**)&w2h, g_wm2_hi);
    cudaGetSymbolAddress((void**)&w2l, g_wm2_lo);

    static bool attr_set = false;
    if (!attr_set) {
        cudaFuncSetAttribute(flash_attn_w,
            cudaFuncAttributeMaxDynamicSharedMemorySize, FAW_SMEM);
        cudaFuncSetAttribute(wm_gemm<1>,
            cudaFuncAttributeMaxDynamicSharedMemorySize, GEMM_SMEM);
        cudaFuncSetAttribute(wm_gemm<2>,
            cudaFuncAttributeMaxDynamicSharedMemorySize, GEMM_SMEM);
        cudaFuncSetAttribute(wm_gemm<3>,
            cudaFuncAttributeMaxDynamicSharedMemorySize, GEMM_SMEM);
        cudaStreamCreateWithFlags(&g_side, cudaStreamNonBlocking);
        cudaEventCreateWithFlags(&g_ev_fork, cudaEventDisableTiming);
        cudaEventCreateWithFlags(&g_ev_qkvw, cudaEventDisableTiming);
        cudaEventCreateWithFlags(&g_ev_allw, cudaEventDisableTiming);
        attr_set = true;
    }

    const dim3 tb(32, 8);

    // --- fork: weight splits on the side stream ---
    cudaEventRecord(g_ev_fork, 0);
    cudaStreamWaitEvent(g_side, g_ev_fork, 0);
    wsplit_t<<<dim3(3 * D_ / 32, D_ / 32), tb, 0, g_side>>>(
        w_qkv, wqh, wql, D_, 3 * D_);
    cudaEventRecord(g_ev_qkvw, g_side);
    wsplit_t<<<dim3(D_ / 32, D_ / 32), tb, 0, g_side>>>(
        w_proj, wph, wpl, D_, D_);
    wsplit_t<<<dim3(F_ / 32, D_ / 32), tb, 0, g_side>>>(
        w_mlp1, w1h, w1l, D_, F_);
    wsplit_t<<<dim3(D_ / 32, F_ / 32), tb, 0, g_side>>>(
        w_mlp2, w2h, w2l, F_, D_);
    cudaEventRecord(g_ev_allw, g_side);

    // --- main chain (default stream), overlapping the splits ---
    // 1) pre-norm 1 -> bf16 hi/lo (independent of weights)
    layernorm_k<<<M_, 256>>>(x, ln1_s, ln1_b, hhi, hlo);
    // join: qkv weights ready
    cudaStreamWaitEvent(0, g_ev_qkvw, 0);
    // 2) qkv projection -> bf16 hi/lo
    wm_gemm<3><<<dim3(3 * D_ / BN, M_ / BM), 256, GEMM_SMEM>>>(
        hhi, hlo, wqh, wql, nullptr, nullptr, nullptr, qkvh, qkvl,
        M_, 3 * D_, D_);
    // 3) attention -> bf16 hi/lo (proj/mlp splits still hiding under this)
    flash_attn_w<<<dim3(L_ / 64, H_, B_), 128, FAW_SMEM>>>(
        qkvh, qkvl, athi, atlo);
    // join: all remaining weights ready
    cudaStreamWaitEvent(0, g_ev_allw, 0);
    // 4) out proj + bias + residual -> fp32 x1
    wm_gemm<1><<<dim3(D_ / BN, M_ / BM), 256, GEMM_SMEM>>>(
        athi, atlo, wph, wpl, b_proj, x, x1, nullptr, nullptr,
        M_, D_, D_);
    // 5) pre-norm 2 -> bf16 hi/lo
    layernorm_k<<<M_, 256>>>(x1, ln2_s, ln2_b, hhi, hlo);
    // 6) MLP up + bias + gelu -> bf16 hi/lo
    wm_gemm<2><<<dim3(F_ / BN, M_ / BM), 256, GEMM_SMEM>>>(
        hhi, hlo, w1h, w1l, b_mlp1, nullptr, nullptr, midhi, midlo,
        M_, F_, D_);
    // 7) MLP down + bias + residual -> final out
    wm_gemm<1><<<dim3(D_ / BN, M_ / BM), 256, GEMM_SMEM>>>(
        midhi, midlo, w2h, w2l, b_mlp2, x1, out, nullptr, nullptr,
        M_, D_, F_);
}